// round 14
// baseline (speedup 1.0000x reference)
#include <cuda_runtime.h>
#include <cuda_bf16.h>
#include <cstdint>
#include <cstddef>
#include <cfloat>

// Problem constants
#define BB   32
#define CIN  128
#define MID  256
#define HH   64
#define WW   64
#define NCLS 65
#define HI   512
#define WI   512
#define CONF 0.015f

// ---------------- scratch (device globals) ----------------
__device__ __nv_bfloat16 g_hhi[(size_t)BB * HH * WW * MID];  // [px][oc] hi
__device__ __nv_bfloat16 g_hlo[(size_t)BB * HH * WW * MID];  // [px][oc] lo
__device__ __nv_bfloat16 g_whi[MID * 1152];                  // [oc][(r*3+s)*128+c]
__device__ __nv_bfloat16 g_wlo[MID * 1152];
__device__ __nv_bfloat16 g_w2hi[80 * 256];                   // [cls(pad80)][oc]
__device__ __nv_bfloat16 g_w2lo[80 * 256];
// channel-last activations, y and x padded by 1 each side: [b][yy=0..65][ww=0..65][c]
__device__ __nv_bfloat16 g_xc_hi[(size_t)BB * 66 * 66 * 128];
__device__ __nv_bfloat16 g_xc_lo[(size_t)BB * 66 * 66 * 128];
__device__ float g_scores[(size_t)BB * HI * WI];
__device__ unsigned char g_mask_a[(size_t)BB * HI * WI];
__device__ unsigned char g_mask_b[(size_t)BB * HI * WI];
__device__ int g_changed[8];

// ---------------- small PTX helpers (all sm_80+ standard) ----------------
__device__ __forceinline__ uint32_t smem_to_u32(const void* p) {
    uint32_t a;
    asm("{ .reg .u64 t; cvta.to.shared.u64 t, %1; cvt.u32.u64 %0, t; }" : "=r"(a) : "l"(p));
    return a;
}
__device__ __forceinline__ void cp_async16(uint32_t dst, const void* src) {
    asm volatile("cp.async.cg.shared.global [%0], [%1], 16;" :: "r"(dst), "l"(src));
}
__device__ __forceinline__ void cp_commit() { asm volatile("cp.async.commit_group;"); }
__device__ __forceinline__ void cp_wait0()  { asm volatile("cp.async.wait_group 0;"); }

__device__ __forceinline__ void ldmx4(uint32_t* r, uint32_t addr) {
    asm volatile("ldmatrix.sync.aligned.m8n8.x4.shared.b16 {%0,%1,%2,%3}, [%4];"
                 : "=r"(r[0]), "=r"(r[1]), "=r"(r[2]), "=r"(r[3]) : "r"(addr));
}
__device__ __forceinline__ void mma16816(float* c, const uint32_t* a, const uint32_t* b) {
    asm volatile("mma.sync.aligned.m16n8k16.row.col.f32.bf16.bf16.f32 "
                 "{%0,%1,%2,%3}, {%4,%5,%6,%7}, {%8,%9}, {%0,%1,%2,%3};"
                 : "+f"(c[0]), "+f"(c[1]), "+f"(c[2]), "+f"(c[3])
                 : "r"(a[0]), "r"(a[1]), "r"(a[2]), "r"(a[3]), "r"(b[0]), "r"(b[1]));
}
__device__ __forceinline__ uint32_t swz(uint32_t off) { return off ^ ((off >> 3) & 0x70); }
__device__ __forceinline__ unsigned short bfu(float v) {
    __nv_bfloat16 h = __float2bfloat16_rn(v);
    return *(unsigned short*)&h;
}
__device__ __forceinline__ float bff(unsigned short u) {
    __nv_bfloat16 h = *(__nv_bfloat16*)&u;
    return __bfloat162float(h);
}

// ---------------- prep kernels ----------------
// blocks [0,1152): w1 split; blocks [1152,1232): w2 split.
__global__ void k_prep_w(const float* __restrict__ w1, const float* __restrict__ w2) {
    if (blockIdx.x < 1152) {
        int idx = blockIdx.x * 256 + threadIdx.x;      // 256*1152
        int oc = idx / 1152;
        int rem = idx - oc * 1152;
        int rs = rem >> 7, c = rem & 127;
        float v = w1[oc * 1152 + c * 9 + rs];
        __nv_bfloat16 hi = __float2bfloat16_rn(v);
        g_whi[idx] = hi;
        g_wlo[idx] = __float2bfloat16_rn(v - __bfloat162float(hi));
    } else {
        int idx = (blockIdx.x - 1152) * 256 + threadIdx.x;  // 80*256
        int cls = idx >> 8;
        float v = (cls < NCLS) ? w2[idx] : 0.f;
        __nv_bfloat16 hi = __float2bfloat16_rn(v);
        g_w2hi[idx] = hi;
        g_w2lo[idx] = __float2bfloat16_rn(v - __bfloat162float(hi));
    }
}

// Transpose x to channel-last, padded by 1 in y and x: g_xc[b][yy][ww][c].
__global__ __launch_bounds__(256) void k_prep_x(const float* __restrict__ x) {
    __shared__ float sm[128][65];
    const int yy = blockIdx.x;   // 0..65
    const int b  = blockIdx.y;
    const int tid = threadIdx.x;
    const int y = yy - 1;
    const bool valid_y = (y >= 0 && y < HH);
    if (valid_y) {
        for (int idx = tid; idx < 2048; idx += 256) {
            int c = idx >> 4, v = idx & 15;
            float4 val = *(const float4*)&x[(((size_t)b * CIN + c) * HH + y) * WW + v * 4];
            sm[c][v * 4 + 0] = val.x; sm[c][v * 4 + 1] = val.y;
            sm[c][v * 4 + 2] = val.z; sm[c][v * 4 + 3] = val.w;
        }
    }
    __syncthreads();
    for (int idx = tid; idx < 66 * 16; idx += 256) {   // 66 ww x 16 cvec
        int ww = idx >> 4, cv = idx & 15;
        int c0 = cv * 8;
        int xw = ww - 1;
        union { unsigned short u16[8]; uint4 v; } Hq, Lq;
        if (valid_y && xw >= 0 && xw < WW) {
#pragma unroll
            for (int e = 0; e < 8; ++e) {
                float vv = sm[c0 + e][xw];
                unsigned short h = bfu(vv);
                Hq.u16[e] = h;
                Lq.u16[e] = bfu(vv - bff(h));
            }
        } else {
            Hq.v = make_uint4(0, 0, 0, 0);
            Lq.v = make_uint4(0, 0, 0, 0);
        }
        size_t ofs = (((size_t)b * 66 + yy) * 66 + ww) * 128 + c0;
        *(uint4*)&g_xc_hi[ofs] = Hq.v;
        *(uint4*)&g_xc_lo[ofs] = Lq.v;
    }
}

// ---------------- conv1 via mma.sync (double-buffered) ----------
#define STG_BYTES 65536
#define SMEM_C1 (2 * STG_BYTES)
__global__ __launch_bounds__(256, 1) void k_conv1_mma(const float* __restrict__ b1) {
    extern __shared__ char smem[];
    const uint32_t smem_u = smem_to_u32(smem);
    const int tid = threadIdx.x;
    const int lane = tid & 31;
    const int wid = tid >> 5;
    const int warpM = wid & 1;
    const int warpN = wid >> 1;
    const int o0g = blockIdx.x * 128;
    const int py0 = blockIdx.y * 2;
    const int bb  = blockIdx.z;

    float acc[4][4][4];
#pragma unroll
    for (int i = 0; i < 4; ++i)
#pragma unroll
        for (int j = 0; j < 4; ++j)
#pragma unroll
            for (int e = 0; e < 4; ++e) acc[i][j][e] = 0.f;

    auto fill = [&](int t, int buf) {
        const int rs = t >> 1;
        const int c0 = (t & 1) * 64;
        const int r = rs / 3, s = rs - r * 3;
        const uint32_t stg = smem_u + buf * STG_BYTES;
#pragma unroll
        for (int i = 0; i < 8; ++i) {
            int idx = tid + i * 256;
            int half = idx >> 10;
            int row  = (idx >> 3) & 127;
            int v    = idx & 7;
            const __nv_bfloat16* wseg = half ? g_wlo : g_whi;
            const void* src = wseg + (size_t)(o0g + row) * 1152 + rs * 128 + c0 + v * 8;
            cp_async16(stg + half * 16384 + swz((uint32_t)(row * 128 + v * 16)), src);
        }
        const size_t xb = (size_t)bb * 66;
#pragma unroll
        for (int i = 0; i < 8; ++i) {
            int idx = tid + i * 256;
            int half = idx >> 10;
            int row  = (idx >> 3) & 127;
            int v    = idx & 7;
            int j = row >> 6, w = row & 63;
            const __nv_bfloat16* xseg = half ? g_xc_lo : g_xc_hi;
            const void* src = xseg + ((xb + (py0 + j + r)) * 66 + (w + s)) * 128 + c0 + v * 8;
            cp_async16(stg + 32768 + half * 16384 + swz((uint32_t)(row * 128 + v * 16)), src);
        }
        cp_commit();
    };

    fill(0, 0);
    cp_wait0();
    __syncthreads();

    const int m0w = warpM * 64;
    const int n0w = warpN * 32;

    for (int t = 0; t < 18; ++t) {
        const int cur = t & 1;
        if (t + 1 < 18) fill(t + 1, cur ^ 1);
        const uint32_t stg = smem_u + cur * STG_BYTES;
#pragma unroll
        for (int k16 = 0; k16 < 4; ++k16) {
            uint32_t afh[4][4], afl[4][4], bfh[4][2], bfl[4][2];
            const uint32_t kbyte = (uint32_t)(k16 * 16 + 8 * (lane >> 4)) * 2;
#pragma unroll
            for (int mf = 0; mf < 4; ++mf) {
                uint32_t roff = (uint32_t)(m0w + mf * 16 + (lane & 15)) * 128;
                ldmx4(afh[mf], stg + swz(roff + kbyte));
                ldmx4(afl[mf], stg + 16384 + swz(roff + kbyte));
            }
#pragma unroll
            for (int pair = 0; pair < 2; ++pair) {
                int n = n0w + pair * 16 + (lane & 7) + 8 * (lane >> 4);
                uint32_t koff = (uint32_t)(k16 * 16 + 8 * ((lane >> 3) & 1)) * 2;
                uint32_t boff = swz((uint32_t)n * 128 + koff);
                uint32_t r4[4];
                ldmx4(r4, stg + 32768 + boff);
                bfh[pair * 2][0] = r4[0]; bfh[pair * 2][1] = r4[1];
                bfh[pair * 2 + 1][0] = r4[2]; bfh[pair * 2 + 1][1] = r4[3];
                ldmx4(r4, stg + 49152 + boff);
                bfl[pair * 2][0] = r4[0]; bfl[pair * 2][1] = r4[1];
                bfl[pair * 2 + 1][0] = r4[2]; bfl[pair * 2 + 1][1] = r4[3];
            }
#pragma unroll
            for (int mf = 0; mf < 4; ++mf)
#pragma unroll
                for (int nf = 0; nf < 4; ++nf) {
                    mma16816(acc[mf][nf], afh[mf], bfh[nf]);
                    mma16816(acc[mf][nf], afh[mf], bfl[nf]);
                    mma16816(acc[mf][nf], afl[mf], bfh[nf]);
                }
        }
        cp_wait0();
        __syncthreads();
    }

    // ---- epilogue: stage [64 px][128 oc], bias+relu, emit bf16 hi/lo ----
    float* ep = (float*)smem;
    const size_t pxbase = (size_t)bb * 4096 + (size_t)py0 * 64;
#pragma unroll
    for (int half = 0; half < 2; ++half) {
        __syncthreads();
        if ((warpN >> 1) == half) {
            const int nloc = (warpN & 1) * 32;
#pragma unroll
            for (int mf = 0; mf < 4; ++mf)
#pragma unroll
                for (int nf = 0; nf < 4; ++nf) {
                    int mm = m0w + mf * 16 + (lane >> 2);
                    int nn = nloc + nf * 8 + (lane & 3) * 2;
                    ep[nn * 132 + mm]           = acc[mf][nf][0];
                    ep[(nn + 1) * 132 + mm]     = acc[mf][nf][1];
                    ep[nn * 132 + mm + 8]       = acc[mf][nf][2];
                    ep[(nn + 1) * 132 + mm + 8] = acc[mf][nf][3];
                }
        }
        __syncthreads();
#pragma unroll
        for (int i = 0; i < 8; ++i) {
            int idx = tid + i * 256;
            int row = idx >> 5, vo = idx & 31;
            float4 bv = *(const float4*)&b1[o0g + vo * 4];
            float v0 = fmaxf(ep[row * 132 + vo * 4 + 0] + bv.x, 0.f);
            float v1 = fmaxf(ep[row * 132 + vo * 4 + 1] + bv.y, 0.f);
            float v2 = fmaxf(ep[row * 132 + vo * 4 + 2] + bv.z, 0.f);
            float v3 = fmaxf(ep[row * 132 + vo * 4 + 3] + bv.w, 0.f);
            union { unsigned short u[4]; uint2 v; } Hq, Lq;
            Hq.u[0] = bfu(v0); Lq.u[0] = bfu(v0 - bff(Hq.u[0]));
            Hq.u[1] = bfu(v1); Lq.u[1] = bfu(v1 - bff(Hq.u[1]));
            Hq.u[2] = bfu(v2); Lq.u[2] = bfu(v2 - bff(Hq.u[2]));
            Hq.u[3] = bfu(v3); Lq.u[3] = bfu(v3 - bff(Hq.u[3]));
            size_t px = pxbase + half * 64 + row;
            *(uint2*)&g_hhi[px * MID + o0g + vo * 4] = Hq.v;
            *(uint2*)&g_hlo[px * MID + o0g + vo * 4] = Lq.v;
        }
    }
}

// ---------------- conv2 via mma.sync + fused softmax/threshold/d2s ----------------
#define C2_A_BYTES 81920
#define C2_B_OFF   C2_A_BYTES
#define C2_B_BUF   32768
#define SMEM_C2    (C2_A_BYTES + 2 * C2_B_BUF)
#define EP_STRIDE  85
__global__ __launch_bounds__(256, 1) void k_conv2_mma(const float* __restrict__ b2) {
    extern __shared__ char smem[];
    const uint32_t smem_u = smem_to_u32(smem);
    const int tid = threadIdx.x;
    const int lane = tid & 31;
    const int wid = tid >> 5;
    const int n0 = wid * 16;
    const int p0 = blockIdx.x * 128;

#pragma unroll
    for (int i = 0; i < 20; ++i) {
        int idx = tid + i * 256;
        int chunk = idx / 1280;
        int rem = idx - chunk * 1280;
        int half = rem / 640;
        int rr = rem - half * 640;
        int row = rr >> 3, v = rr & 7;
        const __nv_bfloat16* src = (half ? g_w2lo : g_w2hi) + row * 256 + chunk * 64 + v * 8;
        cp_async16(smem_u + chunk * 20480 + half * 10240 + swz((uint32_t)(row * 128 + v * 16)), src);
    }
    auto fillB = [&](int kc, int buf) {
#pragma unroll
        for (int i = 0; i < 8; ++i) {
            int idx = tid + i * 256;
            int half = idx >> 10;
            int row  = (idx >> 3) & 127;
            int v    = idx & 7;
            const __nv_bfloat16* src = (half ? g_hlo : g_hhi) + (size_t)(p0 + row) * 256 + kc * 64 + v * 8;
            cp_async16(smem_u + C2_B_OFF + buf * C2_B_BUF + half * 16384
                       + swz((uint32_t)(row * 128 + v * 16)), src);
        }
        cp_commit();
    };
    fillB(0, 0);
    cp_wait0();
    __syncthreads();

    float acc[5][2][4];
#pragma unroll
    for (int i = 0; i < 5; ++i)
#pragma unroll
        for (int j = 0; j < 2; ++j)
#pragma unroll
            for (int e = 0; e < 4; ++e) acc[i][j][e] = 0.f;

    for (int kc = 0; kc < 4; ++kc) {
        const int cur = kc & 1;
        if (kc + 1 < 4) fillB(kc + 1, cur ^ 1);
        const uint32_t abase = smem_u + kc * 20480;
        const uint32_t bbase = smem_u + C2_B_OFF + cur * C2_B_BUF;
#pragma unroll
        for (int k16 = 0; k16 < 4; ++k16) {
            uint32_t ah[5][4], al[5][4], bh[2][2], bl[2][2];
            const uint32_t kbyte = (uint32_t)(k16 * 16 + 8 * (lane >> 4)) * 2;
#pragma unroll
            for (int mf = 0; mf < 5; ++mf) {
                uint32_t roff = (uint32_t)(mf * 16 + (lane & 15)) * 128;
                ldmx4(ah[mf], abase + swz(roff + kbyte));
                ldmx4(al[mf], abase + 10240 + swz(roff + kbyte));
            }
            {
                int n = n0 + (lane & 7) + 8 * (lane >> 4);
                uint32_t koff = (uint32_t)(k16 * 16 + 8 * ((lane >> 3) & 1)) * 2;
                uint32_t boff = swz((uint32_t)n * 128 + koff);
                uint32_t r4[4];
                ldmx4(r4, bbase + boff);
                bh[0][0] = r4[0]; bh[0][1] = r4[1]; bh[1][0] = r4[2]; bh[1][1] = r4[3];
                ldmx4(r4, bbase + 16384 + boff);
                bl[0][0] = r4[0]; bl[0][1] = r4[1]; bl[1][0] = r4[2]; bl[1][1] = r4[3];
            }
#pragma unroll
            for (int mf = 0; mf < 5; ++mf)
#pragma unroll
                for (int nf = 0; nf < 2; ++nf) {
                    mma16816(acc[mf][nf], ah[mf], bh[nf]);
                    mma16816(acc[mf][nf], ah[mf], bl[nf]);
                    mma16816(acc[mf][nf], al[mf], bh[nf]);
                }
        }
        cp_wait0();
        __syncthreads();
    }

    float* ep = (float*)(smem + C2_B_OFF);
#pragma unroll
    for (int mf = 0; mf < 5; ++mf)
#pragma unroll
        for (int nf = 0; nf < 2; ++nf) {
            int mm = mf * 16 + (lane >> 2);
            int nn = n0 + nf * 8 + (lane & 3) * 2;
            ep[nn * EP_STRIDE + mm]           = acc[mf][nf][0];
            ep[(nn + 1) * EP_STRIDE + mm]     = acc[mf][nf][1];
            ep[nn * EP_STRIDE + mm + 8]       = acc[mf][nf][2];
            ep[(nn + 1) * EP_STRIDE + mm + 8] = acc[mf][nf][3];
        }
    __syncthreads();

    if (tid < 128) {
        const int p = p0 + tid;
        float a[NCLS];
#pragma unroll
        for (int i = 0; i < NCLS; ++i) a[i] = ep[tid * EP_STRIDE + i] + __ldg(&b2[i]);
        float m = a[0];
#pragma unroll
        for (int i = 1; i < NCLS; ++i) m = fmaxf(m, a[i]);
        float ssum = 0.f;
#pragma unroll
        for (int i = 0; i < NCLS; ++i) { float e = expf(a[i] - m); a[i] = e; ssum += e; }
        const float inv = 1.f / ssum;
        int b = p >> 12;
        int rem = p & 4095;
        int y = rem >> 6;
        int w = rem & 63;
#pragma unroll
        for (int r1 = 0; r1 < 8; ++r1) {
            size_t base = ((size_t)(b * HI) + y * 8 + r1) * WI + w * 8;
#pragma unroll
            for (int r2 = 0; r2 < 8; ++r2) {
                float pr = a[r1 * 8 + r2] * inv;
                g_scores[base + r2] = (pr >= CONF) ? pr : 0.f;
            }
        }
    }
}

// ---------------- fused row+col max (radius 4) -> init mask ----------------
__global__ __launch_bounds__(256) void k_initmask() {
    const int x0 = blockIdx.x * 64;
    const int y0 = blockIdx.y * 32;
    const int b  = blockIdx.z;
    const int tid = threadIdx.x;
    if (blockIdx.x == 0 && blockIdx.y == 0 && blockIdx.z == 0 && tid < 8)
        g_changed[tid] = 0;
    __shared__ float sm[40][72];
    __shared__ float rm[40][64];
    for (int idx = tid; idx < 40 * 72; idx += 256) {
        int ly = idx / 72, j = idx - ly * 72;
        int gy = y0 - 4 + ly, gx = x0 - 4 + j;
        sm[ly][j] = (gy >= 0 && gy < HI && gx >= 0 && gx < WI)
            ? g_scores[((size_t)b * HI + gy) * WI + gx] : -FLT_MAX;
    }
    __syncthreads();
    for (int idx = tid; idx < 40 * 64; idx += 256) {
        int ly = idx >> 6, lx = idx & 63;
        float m = sm[ly][lx];
#pragma unroll
        for (int d = 1; d <= 8; ++d) m = fmaxf(m, sm[ly][lx + d]);
        rm[ly][lx] = m;
    }
    __syncthreads();
    for (int idx = tid; idx < 32 * 64; idx += 256) {
        int oy = idx >> 6, ox = idx & 63;
        float m = rm[oy][ox];
#pragma unroll
        for (int d = 1; d <= 8; ++d) m = fmaxf(m, rm[oy + d][ox]);
        size_t g = ((size_t)b * HI + y0 + oy) * WI + x0 + ox;
        float s = g_scores[g];
        g_mask_a[g] = (s == m && s > 0.f) ? 1 : 0;
    }
}

// ---------------- one NMS iteration with convergence skip -------
// iter i in [1,6]: if iteration i-1 changed nothing, the fixpoint is reached and
// this iteration is a no-op -> return (no copy needed; buffer parity derived
// from the count of changed iterations). iter 7 always runs and emits output.
__global__ __launch_bounds__(256) void k_nms_iter(int iter, float* __restrict__ out) {
    // count changed iterations before this one (prefix-stable during this launch)
    int cnt = 0;
    for (int j = 0; j < iter; ++j) cnt += (g_changed[j] != 0) ? 1 : 0;
    const int last = (iter == 7);
    if (!last && iter > 0 && g_changed[iter - 1] == 0) return;

    const int src = cnt & 1;
    const unsigned char* min_ = src ? g_mask_b : g_mask_a;
    unsigned char*       mout = src ? g_mask_a : g_mask_b;
    const int x0 = blockIdx.x * 32;
    const int y0 = blockIdx.y * 32;
    const int b  = blockIdx.z;
    const int tid = threadIdx.x;
    const int lane = tid & 31;

    __shared__ float ssc[48][48];
    __shared__ float ss2[48][48];
    __shared__ float rmx[48][48];
    __shared__ unsigned char msk[48][48];
    __shared__ unsigned char dil[48][48];
    __shared__ unsigned char sup[48][48];

    for (int idx = tid; idx < 48 * 48; idx += 256) {
        int ly = idx / 48, lx = idx - ly * 48;
        int gy = y0 - 8 + ly, gx = x0 - 8 + lx;
        float sv = 0.f; unsigned char mv = 0;
        if (gy >= 0 && gy < HI && gx >= 0 && gx < WI) {
            size_t g = ((size_t)b * HI + gy) * WI + gx;
            sv = g_scores[g]; mv = min_[g];
        }
        ssc[ly][lx] = sv; msk[ly][lx] = mv;
    }
    __syncthreads();
    for (int idx = tid; idx < 48 * 40; idx += 256) {
        int y = idx / 40, x = 4 + (idx - (idx / 40) * 40);
        unsigned char m = 0;
#pragma unroll
        for (int d = -4; d <= 4; ++d) m |= msk[y][x + d];
        dil[y][x] = m;
    }
    __syncthreads();
    for (int idx = tid; idx < 40 * 40; idx += 256) {
        int y = 4 + idx / 40, x = 4 + (idx % 40);
        unsigned char m = 0;
#pragma unroll
        for (int d = -4; d <= 4; ++d) m |= dil[y + d][x];
        sup[y][x] = m;
        ss2[y][x] = m ? 0.f : ssc[y][x];
    }
    __syncthreads();
    for (int idx = tid; idx < 40 * 32; idx += 256) {
        int y = 4 + idx / 32, x = 8 + (idx & 31);
        float m = ss2[y][x - 4];
#pragma unroll
        for (int d = -3; d <= 4; ++d) m = fmaxf(m, ss2[y][x + d]);
        rmx[y][x] = m;
    }
    __syncthreads();
    bool ch = false;
    for (int idx = tid; idx < 32 * 32; idx += 256) {
        int y = 8 + (idx >> 5), x = 8 + (idx & 31);
        float m = rmx[y - 4][x];
#pragma unroll
        for (int d = -3; d <= 4; ++d) m = fmaxf(m, rmx[y + d][x]);
        float v = ss2[y][x];
        unsigned char nm = (v == m && v > 0.f) ? 1 : 0;
        unsigned char o = msk[y][x] | (unsigned char)(nm & (sup[y][x] ? 0 : 1));
        ch |= (o != msk[y][x]);
        int gy = y0 + y - 8, gx = x0 + x - 8;
        if (!last) {
            mout[((size_t)b * HI + gy) * WI + gx] = o;
        } else {
            bool border = (gy >= 4 && gy < HI - 4 && gx >= 4 && gx < WI - 4);
            out[((size_t)b * HI + gy) * WI + gx] = (o && border) ? ssc[y][x] : 0.f;
        }
    }
    if (!last) {
        unsigned ball = __ballot_sync(0xFFFFFFFFu, ch);
        if (ball && lane == 0) g_changed[iter] = 1;
    }
}

// ---------------- launch ----------------
extern "C" void kernel_launch(void* const* d_in, const int* in_sizes, int n_in,
                              void* d_out, int out_size) {
    const float* x  = (const float*)d_in[0];
    const float* w1 = (const float*)d_in[1];
    const float* b1 = (const float*)d_in[2];
    const float* w2 = (const float*)d_in[3];
    const float* b2 = (const float*)d_in[4];
    float* out = (float*)d_out;

    cudaFuncSetAttribute(k_conv1_mma, cudaFuncAttributeMaxDynamicSharedMemorySize, SMEM_C1);
    cudaFuncSetAttribute(k_conv2_mma, cudaFuncAttributeMaxDynamicSharedMemorySize, SMEM_C2);

    k_prep_w<<<1232, 256>>>(w1, w2);
    k_prep_x<<<dim3(66, 32), 256>>>(x);
    k_conv1_mma<<<dim3(2, 32, 32), 256, SMEM_C1>>>(b1);
    k_conv2_mma<<<1024, 256, SMEM_C2>>>(b2);
    k_initmask<<<dim3(8, 16, 32), 256>>>();
    for (int i = 0; i < 8; ++i)
        k_nms_iter<<<dim3(16, 16, 32), 256>>>(i, out);
}

// round 15
// speedup vs baseline: 1.1104x; 1.1104x over previous
#include <cuda_runtime.h>
#include <cuda_bf16.h>
#include <cstdint>
#include <cstddef>
#include <cfloat>

// Problem constants
#define BB   32
#define CIN  128
#define MID  256
#define HH   64
#define WW   64
#define NCLS 65
#define HI   512
#define WI   512
#define CONF 0.015f

// ---------------- scratch (device globals) ----------------
__device__ __nv_bfloat16 g_hhi[(size_t)BB * HH * WW * MID];  // [px][oc] hi
__device__ __nv_bfloat16 g_hlo[(size_t)BB * HH * WW * MID];  // [px][oc] lo
__device__ __nv_bfloat16 g_whi[MID * 1152];                  // [oc][(r*3+s)*128+c]
__device__ __nv_bfloat16 g_wlo[MID * 1152];
__device__ __nv_bfloat16 g_w2hi[80 * 256];                   // [cls(pad80)][oc]
__device__ __nv_bfloat16 g_w2lo[80 * 256];
// channel-last activations, y and x padded by 1 each side: [b][yy=0..65][ww=0..65][c]
__device__ __nv_bfloat16 g_xc_hi[(size_t)BB * 66 * 66 * 128];
__device__ __nv_bfloat16 g_xc_lo[(size_t)BB * 66 * 66 * 128];
__device__ float g_scores[(size_t)BB * HI * WI];
__device__ unsigned char g_mask_a[(size_t)BB * HI * WI];
__device__ unsigned char g_mask_b[(size_t)BB * HI * WI];

// ---------------- small PTX helpers (all sm_80+ standard) ----------------
__device__ __forceinline__ uint32_t smem_to_u32(const void* p) {
    uint32_t a;
    asm("{ .reg .u64 t; cvta.to.shared.u64 t, %1; cvt.u32.u64 %0, t; }" : "=r"(a) : "l"(p));
    return a;
}
__device__ __forceinline__ void cp_async16(uint32_t dst, const void* src) {
    asm volatile("cp.async.cg.shared.global [%0], [%1], 16;" :: "r"(dst), "l"(src));
}
__device__ __forceinline__ void cp_commit() { asm volatile("cp.async.commit_group;"); }
__device__ __forceinline__ void cp_wait0()  { asm volatile("cp.async.wait_group 0;"); }
__device__ __forceinline__ void cp_wait1()  { asm volatile("cp.async.wait_group 1;"); }

__device__ __forceinline__ void ldmx4(uint32_t* r, uint32_t addr) {
    asm volatile("ldmatrix.sync.aligned.m8n8.x4.shared.b16 {%0,%1,%2,%3}, [%4];"
                 : "=r"(r[0]), "=r"(r[1]), "=r"(r[2]), "=r"(r[3]) : "r"(addr));
}
__device__ __forceinline__ void mma16816(float* c, const uint32_t* a, const uint32_t* b) {
    asm volatile("mma.sync.aligned.m16n8k16.row.col.f32.bf16.bf16.f32 "
                 "{%0,%1,%2,%3}, {%4,%5,%6,%7}, {%8,%9}, {%0,%1,%2,%3};"
                 : "+f"(c[0]), "+f"(c[1]), "+f"(c[2]), "+f"(c[3])
                 : "r"(a[0]), "r"(a[1]), "r"(a[2]), "r"(a[3]), "r"(b[0]), "r"(b[1]));
}
__device__ __forceinline__ uint32_t swz(uint32_t off) { return off ^ ((off >> 3) & 0x70); }
__device__ __forceinline__ unsigned short bfu(float v) {
    __nv_bfloat16 h = __float2bfloat16_rn(v);
    return *(unsigned short*)&h;
}
__device__ __forceinline__ float bff(unsigned short u) {
    __nv_bfloat16 h = *(__nv_bfloat16*)&u;
    return __bfloat162float(h);
}

// ---------------- prep kernels ----------------
// blocks [0,1152): w1 split; blocks [1152,1232): w2 split.
__global__ void k_prep_w(const float* __restrict__ w1, const float* __restrict__ w2) {
    if (blockIdx.x < 1152) {
        int idx = blockIdx.x * 256 + threadIdx.x;      // 256*1152
        int oc = idx / 1152;
        int rem = idx - oc * 1152;
        int rs = rem >> 7, c = rem & 127;
        float v = w1[oc * 1152 + c * 9 + rs];
        __nv_bfloat16 hi = __float2bfloat16_rn(v);
        g_whi[idx] = hi;
        g_wlo[idx] = __float2bfloat16_rn(v - __bfloat162float(hi));
    } else {
        int idx = (blockIdx.x - 1152) * 256 + threadIdx.x;  // 80*256
        int cls = idx >> 8;
        float v = (cls < NCLS) ? w2[idx] : 0.f;
        __nv_bfloat16 hi = __float2bfloat16_rn(v);
        g_w2hi[idx] = hi;
        g_w2lo[idx] = __float2bfloat16_rn(v - __bfloat162float(hi));
    }
}

// Transpose x to channel-last, padded by 1 in y and x: g_xc[b][yy][ww][c].
__global__ __launch_bounds__(256) void k_prep_x(const float* __restrict__ x) {
    __shared__ float sm[128][65];
    const int yy = blockIdx.x;   // 0..65
    const int b  = blockIdx.y;
    const int tid = threadIdx.x;
    const int y = yy - 1;
    const bool valid_y = (y >= 0 && y < HH);
    if (valid_y) {
        for (int idx = tid; idx < 2048; idx += 256) {
            int c = idx >> 4, v = idx & 15;
            float4 val = *(const float4*)&x[(((size_t)b * CIN + c) * HH + y) * WW + v * 4];
            sm[c][v * 4 + 0] = val.x; sm[c][v * 4 + 1] = val.y;
            sm[c][v * 4 + 2] = val.z; sm[c][v * 4 + 3] = val.w;
        }
    }
    __syncthreads();
    for (int idx = tid; idx < 66 * 16; idx += 256) {   // 66 ww x 16 cvec
        int ww = idx >> 4, cv = idx & 15;
        int c0 = cv * 8;
        int xw = ww - 1;
        union { unsigned short u16[8]; uint4 v; } Hq, Lq;
        if (valid_y && xw >= 0 && xw < WW) {
#pragma unroll
            for (int e = 0; e < 8; ++e) {
                float vv = sm[c0 + e][xw];
                unsigned short h = bfu(vv);
                Hq.u16[e] = h;
                Lq.u16[e] = bfu(vv - bff(h));
            }
        } else {
            Hq.v = make_uint4(0, 0, 0, 0);
            Lq.v = make_uint4(0, 0, 0, 0);
        }
        size_t ofs = (((size_t)b * 66 + yy) * 66 + ww) * 128 + c0;
        *(uint4*)&g_xc_hi[ofs] = Hq.v;
        *(uint4*)&g_xc_lo[ofs] = Lq.v;
    }
}

// ---------------- conv1 via mma.sync (3-stage pipeline, no extra sync) ----------
#define STG_BYTES 65536
#define SMEM_C1 (3 * STG_BYTES)
__global__ __launch_bounds__(256, 1) void k_conv1_mma(const float* __restrict__ b1) {
    extern __shared__ char smem[];
    const uint32_t smem_u = smem_to_u32(smem);
    const int tid = threadIdx.x;
    const int lane = tid & 31;
    const int wid = tid >> 5;
    const int warpM = wid & 1;
    const int warpN = wid >> 1;
    const int o0g = blockIdx.x * 128;
    const int py0 = blockIdx.y * 2;
    const int bb  = blockIdx.z;

    float acc[4][4][4];
#pragma unroll
    for (int i = 0; i < 4; ++i)
#pragma unroll
        for (int j = 0; j < 4; ++j)
#pragma unroll
            for (int e = 0; e < 4; ++e) acc[i][j][e] = 0.f;

    auto fill = [&](int t, int buf) {
        const int rs = t >> 1;
        const int c0 = (t & 1) * 64;
        const int r = rs / 3, s = rs - r * 3;
        const uint32_t stg = smem_u + buf * STG_BYTES;
#pragma unroll
        for (int i = 0; i < 8; ++i) {
            int idx = tid + i * 256;
            int half = idx >> 10;
            int row  = (idx >> 3) & 127;
            int v    = idx & 7;
            const __nv_bfloat16* wseg = half ? g_wlo : g_whi;
            const void* src = wseg + (size_t)(o0g + row) * 1152 + rs * 128 + c0 + v * 8;
            cp_async16(stg + half * 16384 + swz((uint32_t)(row * 128 + v * 16)), src);
        }
        const size_t xb = (size_t)bb * 66;
#pragma unroll
        for (int i = 0; i < 8; ++i) {
            int idx = tid + i * 256;
            int half = idx >> 10;
            int row  = (idx >> 3) & 127;
            int v    = idx & 7;
            int j = row >> 6, w = row & 63;
            const __nv_bfloat16* xseg = half ? g_xc_lo : g_xc_hi;
            const void* src = xseg + ((xb + (py0 + j + r)) * 66 + (w + s)) * 128 + c0 + v * 8;
            cp_async16(stg + 32768 + half * 16384 + swz((uint32_t)(row * 128 + v * 16)), src);
        }
        cp_commit();
    };

    fill(0, 0);
    fill(1, 1);

    const int m0w = warpM * 64;
    const int n0w = warpN * 32;

    for (int t = 0; t < 18; ++t) {
        if (t + 1 < 18) cp_wait1(); else cp_wait0();
        __syncthreads();
        const uint32_t stg = smem_u + (t % 3) * STG_BYTES;
#pragma unroll
        for (int k16 = 0; k16 < 4; ++k16) {
            uint32_t afh[4][4], afl[4][4], bfh[4][2], bfl[4][2];
            const uint32_t kbyte = (uint32_t)(k16 * 16 + 8 * (lane >> 4)) * 2;
#pragma unroll
            for (int mf = 0; mf < 4; ++mf) {
                uint32_t roff = (uint32_t)(m0w + mf * 16 + (lane & 15)) * 128;
                ldmx4(afh[mf], stg + swz(roff + kbyte));
                ldmx4(afl[mf], stg + 16384 + swz(roff + kbyte));
            }
#pragma unroll
            for (int pair = 0; pair < 2; ++pair) {
                int n = n0w + pair * 16 + (lane & 7) + 8 * (lane >> 4);
                uint32_t koff = (uint32_t)(k16 * 16 + 8 * ((lane >> 3) & 1)) * 2;
                uint32_t boff = swz((uint32_t)n * 128 + koff);
                uint32_t r4[4];
                ldmx4(r4, stg + 32768 + boff);
                bfh[pair * 2][0] = r4[0]; bfh[pair * 2][1] = r4[1];
                bfh[pair * 2 + 1][0] = r4[2]; bfh[pair * 2 + 1][1] = r4[3];
                ldmx4(r4, stg + 49152 + boff);
                bfl[pair * 2][0] = r4[0]; bfl[pair * 2][1] = r4[1];
                bfl[pair * 2 + 1][0] = r4[2]; bfl[pair * 2 + 1][1] = r4[3];
            }
#pragma unroll
            for (int mf = 0; mf < 4; ++mf)
#pragma unroll
                for (int nf = 0; nf < 4; ++nf) {
                    mma16816(acc[mf][nf], afh[mf], bfh[nf]);
                    mma16816(acc[mf][nf], afh[mf], bfl[nf]);
                    mma16816(acc[mf][nf], afl[mf], bfh[nf]);
                }
        }
        // fill stage t+2: its buffer was consumed in iteration t-1; all warps
        // passed this iteration's barrier after finishing it -> safe, no sync.
        if (t + 2 < 18) fill(t + 2, (t + 2) % 3);
    }

    // ---- epilogue: stage [64 px][128 oc], bias+relu, emit bf16 hi/lo ----
    float* ep = (float*)smem;
    const size_t pxbase = (size_t)bb * 4096 + (size_t)py0 * 64;
#pragma unroll
    for (int half = 0; half < 2; ++half) {
        __syncthreads();
        if ((warpN >> 1) == half) {
            const int nloc = (warpN & 1) * 32;
#pragma unroll
            for (int mf = 0; mf < 4; ++mf)
#pragma unroll
                for (int nf = 0; nf < 4; ++nf) {
                    int mm = m0w + mf * 16 + (lane >> 2);
                    int nn = nloc + nf * 8 + (lane & 3) * 2;
                    ep[nn * 132 + mm]           = acc[mf][nf][0];
                    ep[(nn + 1) * 132 + mm]     = acc[mf][nf][1];
                    ep[nn * 132 + mm + 8]       = acc[mf][nf][2];
                    ep[(nn + 1) * 132 + mm + 8] = acc[mf][nf][3];
                }
        }
        __syncthreads();
#pragma unroll
        for (int i = 0; i < 8; ++i) {
            int idx = tid + i * 256;
            int row = idx >> 5, vo = idx & 31;
            float4 bv = *(const float4*)&b1[o0g + vo * 4];
            float v0 = fmaxf(ep[row * 132 + vo * 4 + 0] + bv.x, 0.f);
            float v1 = fmaxf(ep[row * 132 + vo * 4 + 1] + bv.y, 0.f);
            float v2 = fmaxf(ep[row * 132 + vo * 4 + 2] + bv.z, 0.f);
            float v3 = fmaxf(ep[row * 132 + vo * 4 + 3] + bv.w, 0.f);
            union { unsigned short u[4]; uint2 v; } Hq, Lq;
            Hq.u[0] = bfu(v0); Lq.u[0] = bfu(v0 - bff(Hq.u[0]));
            Hq.u[1] = bfu(v1); Lq.u[1] = bfu(v1 - bff(Hq.u[1]));
            Hq.u[2] = bfu(v2); Lq.u[2] = bfu(v2 - bff(Hq.u[2]));
            Hq.u[3] = bfu(v3); Lq.u[3] = bfu(v3 - bff(Hq.u[3]));
            size_t px = pxbase + half * 64 + row;
            *(uint2*)&g_hhi[px * MID + o0g + vo * 4] = Hq.v;
            *(uint2*)&g_hlo[px * MID + o0g + vo * 4] = Lq.v;
        }
    }
}

// ---------------- conv2: 128 threads / 64 px per CTA, A+B double-buffered ------
// Stage: Ahi 10240 | Alo 10240 | Bhi 8192 | Blo 8192 = 36864 B; 2 stages = 73728.
// ~3 CTAs/SM (reg- and smem-feasible) vs 1 before -> hides DRAM latency.
#define ST2_BYTES 36864
#define SMEM_C2   (2 * ST2_BYTES)
#define EP_STRIDE 85
__global__ __launch_bounds__(128, 1) void k_conv2_mma(const float* __restrict__ b2) {
    extern __shared__ char smem[];
    const uint32_t smem_u = smem_to_u32(smem);
    const int tid = threadIdx.x;
    const int lane = tid & 31;
    const int wid = tid >> 5;          // 0..3
    const int n0 = wid * 16;
    const int p0 = blockIdx.x * 64;

    auto fill = [&](int kc, int buf) {
        const uint32_t stg = smem_u + buf * ST2_BYTES;
        // A: 2 halves x 80 rows x 8 vec16 = 1280
        for (int idx = tid; idx < 1280; idx += 128) {
            int half = idx / 640;
            int rr = idx - half * 640;
            int row = rr >> 3, v = rr & 7;
            const __nv_bfloat16* src = (half ? g_w2lo : g_w2hi) + row * 256 + kc * 64 + v * 8;
            cp_async16(stg + half * 10240 + swz((uint32_t)(row * 128 + v * 16)), src);
        }
        // B: 2 halves x 64 rows x 8 vec16 = 1024
        for (int idx = tid; idx < 1024; idx += 128) {
            int half = idx >> 9;
            int row  = (idx >> 3) & 63;
            int v    = idx & 7;
            const __nv_bfloat16* src = (half ? g_hlo : g_hhi) + (size_t)(p0 + row) * 256 + kc * 64 + v * 8;
            cp_async16(stg + 20480 + half * 8192 + swz((uint32_t)(row * 128 + v * 16)), src);
        }
        cp_commit();
    };
    fill(0, 0);
    cp_wait0();
    __syncthreads();

    float acc[5][2][4];
#pragma unroll
    for (int i = 0; i < 5; ++i)
#pragma unroll
        for (int j = 0; j < 2; ++j)
#pragma unroll
            for (int e = 0; e < 4; ++e) acc[i][j][e] = 0.f;

    for (int kc = 0; kc < 4; ++kc) {
        const int cur = kc & 1;
        if (kc + 1 < 4) fill(kc + 1, cur ^ 1);
        const uint32_t stg = smem_u + cur * ST2_BYTES;
#pragma unroll
        for (int k16 = 0; k16 < 4; ++k16) {
            uint32_t ah[5][4], al[5][4], bh[2][2], bl[2][2];
            const uint32_t kbyte = (uint32_t)(k16 * 16 + 8 * (lane >> 4)) * 2;
#pragma unroll
            for (int mf = 0; mf < 5; ++mf) {
                uint32_t roff = (uint32_t)(mf * 16 + (lane & 15)) * 128;
                ldmx4(ah[mf], stg + swz(roff + kbyte));
                ldmx4(al[mf], stg + 10240 + swz(roff + kbyte));
            }
            {
                int n = n0 + (lane & 7) + 8 * (lane >> 4);
                uint32_t koff = (uint32_t)(k16 * 16 + 8 * ((lane >> 3) & 1)) * 2;
                uint32_t boff = swz((uint32_t)n * 128 + koff);
                uint32_t r4[4];
                ldmx4(r4, stg + 20480 + boff);
                bh[0][0] = r4[0]; bh[0][1] = r4[1]; bh[1][0] = r4[2]; bh[1][1] = r4[3];
                ldmx4(r4, stg + 28672 + boff);
                bl[0][0] = r4[0]; bl[0][1] = r4[1]; bl[1][0] = r4[2]; bl[1][1] = r4[3];
            }
#pragma unroll
            for (int mf = 0; mf < 5; ++mf)
#pragma unroll
                for (int nf = 0; nf < 2; ++nf) {
                    mma16816(acc[mf][nf], ah[mf], bh[nf]);
                    mma16816(acc[mf][nf], ah[mf], bl[nf]);
                    mma16816(acc[mf][nf], al[mf], bh[nf]);
                }
        }
        cp_wait0();
        __syncthreads();
    }

    // stage semi [64 px][80 cls] (stride 85)
    float* ep = (float*)smem;
#pragma unroll
    for (int mf = 0; mf < 5; ++mf)
#pragma unroll
        for (int nf = 0; nf < 2; ++nf) {
            int mm = mf * 16 + (lane >> 2);
            int nn = n0 + nf * 8 + (lane & 3) * 2;
            ep[nn * EP_STRIDE + mm]           = acc[mf][nf][0];
            ep[(nn + 1) * EP_STRIDE + mm]     = acc[mf][nf][1];
            ep[nn * EP_STRIDE + mm + 8]       = acc[mf][nf][2];
            ep[(nn + 1) * EP_STRIDE + mm + 8] = acc[mf][nf][3];
        }
    __syncthreads();

    if (tid < 64) {
        const int p = p0 + tid;
        float a[NCLS];
#pragma unroll
        for (int i = 0; i < NCLS; ++i) a[i] = ep[tid * EP_STRIDE + i] + __ldg(&b2[i]);
        float m = a[0];
#pragma unroll
        for (int i = 1; i < NCLS; ++i) m = fmaxf(m, a[i]);
        float ssum = 0.f;
#pragma unroll
        for (int i = 0; i < NCLS; ++i) { float e = expf(a[i] - m); a[i] = e; ssum += e; }
        const float inv = 1.f / ssum;
        int b = p >> 12;
        int rem = p & 4095;
        int y = rem >> 6;
        int w = rem & 63;
#pragma unroll
        for (int r1 = 0; r1 < 8; ++r1) {
            size_t base = ((size_t)(b * HI) + y * 8 + r1) * WI + w * 8;
#pragma unroll
            for (int r2 = 0; r2 < 8; ++r2) {
                float pr = a[r1 * 8 + r2] * inv;
                g_scores[base + r2] = (pr >= CONF) ? pr : 0.f;
            }
        }
    }
}

// ---------------- fused row+col max (radius 4) -> init mask ----------------
__global__ __launch_bounds__(256) void k_initmask() {
    const int x0 = blockIdx.x * 64;
    const int y0 = blockIdx.y * 32;
    const int b  = blockIdx.z;
    const int tid = threadIdx.x;
    __shared__ float sm[40][72];
    __shared__ float rm[40][64];
    for (int idx = tid; idx < 40 * 72; idx += 256) {
        int ly = idx / 72, j = idx - ly * 72;
        int gy = y0 - 4 + ly, gx = x0 - 4 + j;
        sm[ly][j] = (gy >= 0 && gy < HI && gx >= 0 && gx < WI)
            ? g_scores[((size_t)b * HI + gy) * WI + gx] : -FLT_MAX;
    }
    __syncthreads();
    for (int idx = tid; idx < 40 * 64; idx += 256) {
        int ly = idx >> 6, lx = idx & 63;
        float m = sm[ly][lx];
#pragma unroll
        for (int d = 1; d <= 8; ++d) m = fmaxf(m, sm[ly][lx + d]);
        rm[ly][lx] = m;
    }
    __syncthreads();
    for (int idx = tid; idx < 32 * 64; idx += 256) {
        int oy = idx >> 6, ox = idx & 63;
        float m = rm[oy][ox];
#pragma unroll
        for (int d = 1; d <= 8; ++d) m = fmaxf(m, rm[oy + d][ox]);
        size_t g = ((size_t)b * HI + y0 + oy) * WI + x0 + ox;
        float s = g_scores[g];
        g_mask_a[g] = (s == m && s > 0.f) ? 1 : 0;
    }
}

// ---------------- one NMS iteration (round-13 form; last=1 emits output) -------
__global__ __launch_bounds__(256) void k_nms_iter(int flip, int last, float* __restrict__ out) {
    const unsigned char* min_ = flip ? g_mask_b : g_mask_a;
    unsigned char*       mout = flip ? g_mask_a : g_mask_b;
    const int x0 = blockIdx.x * 32;
    const int y0 = blockIdx.y * 32;
    const int b  = blockIdx.z;
    const int tid = threadIdx.x;

    __shared__ float ssc[48][48];
    __shared__ float ss2[48][48];
    __shared__ float rmx[48][48];
    __shared__ unsigned char msk[48][48];
    __shared__ unsigned char dil[48][48];
    __shared__ unsigned char sup[48][48];

    for (int idx = tid; idx < 48 * 48; idx += 256) {
        int ly = idx / 48, lx = idx - ly * 48;
        int gy = y0 - 8 + ly, gx = x0 - 8 + lx;
        float sv = 0.f; unsigned char mv = 0;
        if (gy >= 0 && gy < HI && gx >= 0 && gx < WI) {
            size_t g = ((size_t)b * HI + gy) * WI + gx;
            sv = g_scores[g]; mv = min_[g];
        }
        ssc[ly][lx] = sv; msk[ly][lx] = mv;
    }
    __syncthreads();
    for (int idx = tid; idx < 48 * 40; idx += 256) {
        int y = idx / 40, x = 4 + (idx - (idx / 40) * 40);
        unsigned char m = 0;
#pragma unroll
        for (int d = -4; d <= 4; ++d) m |= msk[y][x + d];
        dil[y][x] = m;
    }
    __syncthreads();
    for (int idx = tid; idx < 40 * 40; idx += 256) {
        int y = 4 + idx / 40, x = 4 + (idx % 40);
        unsigned char m = 0;
#pragma unroll
        for (int d = -4; d <= 4; ++d) m |= dil[y + d][x];
        sup[y][x] = m;
        ss2[y][x] = m ? 0.f : ssc[y][x];
    }
    __syncthreads();
    for (int idx = tid; idx < 40 * 32; idx += 256) {
        int y = 4 + idx / 32, x = 8 + (idx & 31);
        float m = ss2[y][x - 4];
#pragma unroll
        for (int d = -3; d <= 4; ++d) m = fmaxf(m, ss2[y][x + d]);
        rmx[y][x] = m;
    }
    __syncthreads();
    for (int idx = tid; idx < 32 * 32; idx += 256) {
        int y = 8 + (idx >> 5), x = 8 + (idx & 31);
        float m = rmx[y - 4][x];
#pragma unroll
        for (int d = -3; d <= 4; ++d) m = fmaxf(m, rmx[y + d][x]);
        float v = ss2[y][x];
        unsigned char nm = (v == m && v > 0.f) ? 1 : 0;
        unsigned char o = msk[y][x] | (unsigned char)(nm & (sup[y][x] ? 0 : 1));
        int gy = y0 + y - 8, gx = x0 + x - 8;
        if (!last) {
            mout[((size_t)b * HI + gy) * WI + gx] = o;
        } else {
            bool border = (gy >= 4 && gy < HI - 4 && gx >= 4 && gx < WI - 4);
            out[((size_t)b * HI + gy) * WI + gx] = (o && border) ? ssc[y][x] : 0.f;
        }
    }
}

// ---------------- launch ----------------
extern "C" void kernel_launch(void* const* d_in, const int* in_sizes, int n_in,
                              void* d_out, int out_size) {
    const float* x  = (const float*)d_in[0];
    const float* w1 = (const float*)d_in[1];
    const float* b1 = (const float*)d_in[2];
    const float* w2 = (const float*)d_in[3];
    const float* b2 = (const float*)d_in[4];
    float* out = (float*)d_out;

    cudaFuncSetAttribute(k_conv1_mma, cudaFuncAttributeMaxDynamicSharedMemorySize, SMEM_C1);
    cudaFuncSetAttribute(k_conv2_mma, cudaFuncAttributeMaxDynamicSharedMemorySize, SMEM_C2);

    k_prep_w<<<1232, 256>>>(w1, w2);
    k_prep_x<<<dim3(66, 32), 256>>>(x);
    k_conv1_mma<<<dim3(2, 32, 32), 256, SMEM_C1>>>(b1);
    k_conv2_mma<<<2048, 128, SMEM_C2>>>(b2);
    k_initmask<<<dim3(8, 16, 32), 256>>>();
    for (int i = 0; i < 8; ++i)
        k_nms_iter<<<dim3(16, 16, 32), 256>>>(i & 1, (i == 7) ? 1 : 0, out);
}

// round 16
// speedup vs baseline: 1.2430x; 1.1194x over previous
#include <cuda_runtime.h>
#include <cuda_bf16.h>
#include <cstdint>
#include <cstddef>
#include <cfloat>

// Problem constants
#define BB   32
#define CIN  128
#define MID  256
#define HH   64
#define WW   64
#define NCLS 65
#define HI   512
#define WI   512
#define CONF 0.015f

// ---------------- scratch (device globals) ----------------
__device__ __nv_bfloat16 g_hhi[(size_t)BB * HH * WW * MID];  // [px][oc] hi
__device__ __nv_bfloat16 g_hlo[(size_t)BB * HH * WW * MID];  // [px][oc] lo
__device__ __nv_bfloat16 g_whi[MID * 1152];                  // [oc][(r*3+s)*128+c]
__device__ __nv_bfloat16 g_wlo[MID * 1152];
__device__ __nv_bfloat16 g_w2hi[80 * 256];                   // [cls(pad80)][oc]
__device__ __nv_bfloat16 g_w2lo[80 * 256];
// channel-last activations, y and x padded by 1 each side: [b][yy=0..65][ww=0..65][c]
__device__ __nv_bfloat16 g_xc_hi[(size_t)BB * 66 * 66 * 128];
__device__ __nv_bfloat16 g_xc_lo[(size_t)BB * 66 * 66 * 128];
__device__ float g_scores[(size_t)BB * HI * WI];
__device__ unsigned char g_mask_a[(size_t)BB * HI * WI];
__device__ unsigned char g_mask_b[(size_t)BB * HI * WI];

// ---------------- small PTX helpers (all sm_80+ standard) ----------------
__device__ __forceinline__ uint32_t smem_to_u32(const void* p) {
    uint32_t a;
    asm("{ .reg .u64 t; cvta.to.shared.u64 t, %1; cvt.u32.u64 %0, t; }" : "=r"(a) : "l"(p));
    return a;
}
__device__ __forceinline__ void cp_async16(uint32_t dst, const void* src) {
    asm volatile("cp.async.cg.shared.global [%0], [%1], 16;" :: "r"(dst), "l"(src));
}
__device__ __forceinline__ void cp_commit() { asm volatile("cp.async.commit_group;"); }
__device__ __forceinline__ void cp_wait0()  { asm volatile("cp.async.wait_group 0;"); }
__device__ __forceinline__ void cp_wait1()  { asm volatile("cp.async.wait_group 1;"); }

__device__ __forceinline__ void ldmx4(uint32_t* r, uint32_t addr) {
    asm volatile("ldmatrix.sync.aligned.m8n8.x4.shared.b16 {%0,%1,%2,%3}, [%4];"
                 : "=r"(r[0]), "=r"(r[1]), "=r"(r[2]), "=r"(r[3]) : "r"(addr));
}
__device__ __forceinline__ void mma16816(float* c, const uint32_t* a, const uint32_t* b) {
    asm volatile("mma.sync.aligned.m16n8k16.row.col.f32.bf16.bf16.f32 "
                 "{%0,%1,%2,%3}, {%4,%5,%6,%7}, {%8,%9}, {%0,%1,%2,%3};"
                 : "+f"(c[0]), "+f"(c[1]), "+f"(c[2]), "+f"(c[3])
                 : "r"(a[0]), "r"(a[1]), "r"(a[2]), "r"(a[3]), "r"(b[0]), "r"(b[1]));
}
__device__ __forceinline__ uint32_t swz(uint32_t off) { return off ^ ((off >> 3) & 0x70); }
__device__ __forceinline__ unsigned short bfu(float v) {
    __nv_bfloat16 h = __float2bfloat16_rn(v);
    return *(unsigned short*)&h;
}
__device__ __forceinline__ float bff(unsigned short u) {
    __nv_bfloat16 h = *(__nv_bfloat16*)&u;
    return __bfloat162float(h);
}

// ---------------- prep kernels ----------------
// blocks [0,1152): w1 split; blocks [1152,1232): w2 split.
__global__ void k_prep_w(const float* __restrict__ w1, const float* __restrict__ w2) {
    if (blockIdx.x < 1152) {
        int idx = blockIdx.x * 256 + threadIdx.x;      // 256*1152
        int oc = idx / 1152;
        int rem = idx - oc * 1152;
        int rs = rem >> 7, c = rem & 127;
        float v = w1[oc * 1152 + c * 9 + rs];
        __nv_bfloat16 hi = __float2bfloat16_rn(v);
        g_whi[idx] = hi;
        g_wlo[idx] = __float2bfloat16_rn(v - __bfloat162float(hi));
    } else {
        int idx = (blockIdx.x - 1152) * 256 + threadIdx.x;  // 80*256
        int cls = idx >> 8;
        float v = (cls < NCLS) ? w2[idx] : 0.f;
        __nv_bfloat16 hi = __float2bfloat16_rn(v);
        g_w2hi[idx] = hi;
        g_w2lo[idx] = __float2bfloat16_rn(v - __bfloat162float(hi));
    }
}

// Transpose x to channel-last, padded by 1 in y and x: g_xc[b][yy][ww][c].
__global__ __launch_bounds__(256) void k_prep_x(const float* __restrict__ x) {
    __shared__ float sm[128][65];
    const int yy = blockIdx.x;   // 0..65
    const int b  = blockIdx.y;
    const int tid = threadIdx.x;
    const int y = yy - 1;
    const bool valid_y = (y >= 0 && y < HH);
    if (valid_y) {
        for (int idx = tid; idx < 2048; idx += 256) {
            int c = idx >> 4, v = idx & 15;
            float4 val = *(const float4*)&x[(((size_t)b * CIN + c) * HH + y) * WW + v * 4];
            sm[c][v * 4 + 0] = val.x; sm[c][v * 4 + 1] = val.y;
            sm[c][v * 4 + 2] = val.z; sm[c][v * 4 + 3] = val.w;
        }
    }
    __syncthreads();
    for (int idx = tid; idx < 66 * 16; idx += 256) {   // 66 ww x 16 cvec
        int ww = idx >> 4, cv = idx & 15;
        int c0 = cv * 8;
        int xw = ww - 1;
        union { unsigned short u16[8]; uint4 v; } Hq, Lq;
        if (valid_y && xw >= 0 && xw < WW) {
#pragma unroll
            for (int e = 0; e < 8; ++e) {
                float vv = sm[c0 + e][xw];
                unsigned short h = bfu(vv);
                Hq.u16[e] = h;
                Lq.u16[e] = bfu(vv - bff(h));
            }
        } else {
            Hq.v = make_uint4(0, 0, 0, 0);
            Lq.v = make_uint4(0, 0, 0, 0);
        }
        size_t ofs = (((size_t)b * 66 + yy) * 66 + ww) * 128 + c0;
        *(uint4*)&g_xc_hi[ofs] = Hq.v;
        *(uint4*)&g_xc_lo[ofs] = Lq.v;
    }
}

// ---------------- conv1 via mma.sync (3-stage pipeline) ----------
#define STG_BYTES 65536
#define SMEM_C1 (3 * STG_BYTES)
__global__ __launch_bounds__(256, 1) void k_conv1_mma(const float* __restrict__ b1) {
    extern __shared__ char smem[];
    const uint32_t smem_u = smem_to_u32(smem);
    const int tid = threadIdx.x;
    const int lane = tid & 31;
    const int wid = tid >> 5;
    const int warpM = wid & 1;
    const int warpN = wid >> 1;
    const int o0g = blockIdx.x * 128;
    const int py0 = blockIdx.y * 2;
    const int bb  = blockIdx.z;

    float acc[4][4][4];
#pragma unroll
    for (int i = 0; i < 4; ++i)
#pragma unroll
        for (int j = 0; j < 4; ++j)
#pragma unroll
            for (int e = 0; e < 4; ++e) acc[i][j][e] = 0.f;

    auto fill = [&](int t, int buf) {
        const int rs = t >> 1;
        const int c0 = (t & 1) * 64;
        const int r = rs / 3, s = rs - r * 3;
        const uint32_t stg = smem_u + buf * STG_BYTES;
#pragma unroll
        for (int i = 0; i < 8; ++i) {
            int idx = tid + i * 256;
            int half = idx >> 10;
            int row  = (idx >> 3) & 127;
            int v    = idx & 7;
            const __nv_bfloat16* wseg = half ? g_wlo : g_whi;
            const void* src = wseg + (size_t)(o0g + row) * 1152 + rs * 128 + c0 + v * 8;
            cp_async16(stg + half * 16384 + swz((uint32_t)(row * 128 + v * 16)), src);
        }
        const size_t xb = (size_t)bb * 66;
#pragma unroll
        for (int i = 0; i < 8; ++i) {
            int idx = tid + i * 256;
            int half = idx >> 10;
            int row  = (idx >> 3) & 127;
            int v    = idx & 7;
            int j = row >> 6, w = row & 63;
            const __nv_bfloat16* xseg = half ? g_xc_lo : g_xc_hi;
            const void* src = xseg + ((xb + (py0 + j + r)) * 66 + (w + s)) * 128 + c0 + v * 8;
            cp_async16(stg + 32768 + half * 16384 + swz((uint32_t)(row * 128 + v * 16)), src);
        }
        cp_commit();
    };

    fill(0, 0);
    fill(1, 1);

    const int m0w = warpM * 64;
    const int n0w = warpN * 32;

    for (int t = 0; t < 18; ++t) {
        if (t + 1 < 18) cp_wait1(); else cp_wait0();
        __syncthreads();
        const uint32_t stg = smem_u + (t % 3) * STG_BYTES;
#pragma unroll
        for (int k16 = 0; k16 < 4; ++k16) {
            uint32_t afh[4][4], afl[4][4], bfh[4][2], bfl[4][2];
            const uint32_t kbyte = (uint32_t)(k16 * 16 + 8 * (lane >> 4)) * 2;
#pragma unroll
            for (int mf = 0; mf < 4; ++mf) {
                uint32_t roff = (uint32_t)(m0w + mf * 16 + (lane & 15)) * 128;
                ldmx4(afh[mf], stg + swz(roff + kbyte));
                ldmx4(afl[mf], stg + 16384 + swz(roff + kbyte));
            }
#pragma unroll
            for (int pair = 0; pair < 2; ++pair) {
                int n = n0w + pair * 16 + (lane & 7) + 8 * (lane >> 4);
                uint32_t koff = (uint32_t)(k16 * 16 + 8 * ((lane >> 3) & 1)) * 2;
                uint32_t boff = swz((uint32_t)n * 128 + koff);
                uint32_t r4[4];
                ldmx4(r4, stg + 32768 + boff);
                bfh[pair * 2][0] = r4[0]; bfh[pair * 2][1] = r4[1];
                bfh[pair * 2 + 1][0] = r4[2]; bfh[pair * 2 + 1][1] = r4[3];
                ldmx4(r4, stg + 49152 + boff);
                bfl[pair * 2][0] = r4[0]; bfl[pair * 2][1] = r4[1];
                bfl[pair * 2 + 1][0] = r4[2]; bfl[pair * 2 + 1][1] = r4[3];
            }
#pragma unroll
            for (int mf = 0; mf < 4; ++mf)
#pragma unroll
                for (int nf = 0; nf < 4; ++nf) {
                    mma16816(acc[mf][nf], afh[mf], bfh[nf]);
                    mma16816(acc[mf][nf], afh[mf], bfl[nf]);
                    mma16816(acc[mf][nf], afl[mf], bfh[nf]);
                }
        }
        // fill stage t+2: its buffer was consumed in iteration t-1; all warps
        // passed this iteration's barrier after finishing it -> safe, no sync.
        if (t + 2 < 18) fill(t + 2, (t + 2) % 3);
    }

    // ---- epilogue: stage [64 px][128 oc], bias+relu, emit bf16 hi/lo ----
    float* ep = (float*)smem;
    const size_t pxbase = (size_t)bb * 4096 + (size_t)py0 * 64;
#pragma unroll
    for (int half = 0; half < 2; ++half) {
        __syncthreads();
        if ((warpN >> 1) == half) {
            const int nloc = (warpN & 1) * 32;
#pragma unroll
            for (int mf = 0; mf < 4; ++mf)
#pragma unroll
                for (int nf = 0; nf < 4; ++nf) {
                    int mm = m0w + mf * 16 + (lane >> 2);
                    int nn = nloc + nf * 8 + (lane & 3) * 2;
                    ep[nn * 132 + mm]           = acc[mf][nf][0];
                    ep[(nn + 1) * 132 + mm]     = acc[mf][nf][1];
                    ep[nn * 132 + mm + 8]       = acc[mf][nf][2];
                    ep[(nn + 1) * 132 + mm + 8] = acc[mf][nf][3];
                }
        }
        __syncthreads();
#pragma unroll
        for (int i = 0; i < 8; ++i) {
            int idx = tid + i * 256;
            int row = idx >> 5, vo = idx & 31;
            float4 bv = *(const float4*)&b1[o0g + vo * 4];
            float v0 = fmaxf(ep[row * 132 + vo * 4 + 0] + bv.x, 0.f);
            float v1 = fmaxf(ep[row * 132 + vo * 4 + 1] + bv.y, 0.f);
            float v2 = fmaxf(ep[row * 132 + vo * 4 + 2] + bv.z, 0.f);
            float v3 = fmaxf(ep[row * 132 + vo * 4 + 3] + bv.w, 0.f);
            union { unsigned short u[4]; uint2 v; } Hq, Lq;
            Hq.u[0] = bfu(v0); Lq.u[0] = bfu(v0 - bff(Hq.u[0]));
            Hq.u[1] = bfu(v1); Lq.u[1] = bfu(v1 - bff(Hq.u[1]));
            Hq.u[2] = bfu(v2); Lq.u[2] = bfu(v2 - bff(Hq.u[2]));
            Hq.u[3] = bfu(v3); Lq.u[3] = bfu(v3 - bff(Hq.u[3]));
            size_t px = pxbase + half * 64 + row;
            *(uint2*)&g_hhi[px * MID + o0g + vo * 4] = Hq.v;
            *(uint2*)&g_hlo[px * MID + o0g + vo * 4] = Lq.v;
        }
    }
}

// ---------------- conv2: 128 threads / 64 px per CTA, A+B double-buffered ------
#define ST2_BYTES 36864
#define SMEM_C2   (2 * ST2_BYTES)
#define EP_STRIDE 85
__global__ __launch_bounds__(128, 1) void k_conv2_mma(const float* __restrict__ b2) {
    extern __shared__ char smem[];
    const uint32_t smem_u = smem_to_u32(smem);
    const int tid = threadIdx.x;
    const int lane = tid & 31;
    const int wid = tid >> 5;          // 0..3
    const int n0 = wid * 16;
    const int p0 = blockIdx.x * 64;

    auto fill = [&](int kc, int buf) {
        const uint32_t stg = smem_u + buf * ST2_BYTES;
        for (int idx = tid; idx < 1280; idx += 128) {
            int half = idx / 640;
            int rr = idx - half * 640;
            int row = rr >> 3, v = rr & 7;
            const __nv_bfloat16* src = (half ? g_w2lo : g_w2hi) + row * 256 + kc * 64 + v * 8;
            cp_async16(stg + half * 10240 + swz((uint32_t)(row * 128 + v * 16)), src);
        }
        for (int idx = tid; idx < 1024; idx += 128) {
            int half = idx >> 9;
            int row  = (idx >> 3) & 63;
            int v    = idx & 7;
            const __nv_bfloat16* src = (half ? g_hlo : g_hhi) + (size_t)(p0 + row) * 256 + kc * 64 + v * 8;
            cp_async16(stg + 20480 + half * 8192 + swz((uint32_t)(row * 128 + v * 16)), src);
        }
        cp_commit();
    };
    fill(0, 0);
    cp_wait0();
    __syncthreads();

    float acc[5][2][4];
#pragma unroll
    for (int i = 0; i < 5; ++i)
#pragma unroll
        for (int j = 0; j < 2; ++j)
#pragma unroll
            for (int e = 0; e < 4; ++e) acc[i][j][e] = 0.f;

    for (int kc = 0; kc < 4; ++kc) {
        const int cur = kc & 1;
        if (kc + 1 < 4) fill(kc + 1, cur ^ 1);
        const uint32_t stg = smem_u + cur * ST2_BYTES;
#pragma unroll
        for (int k16 = 0; k16 < 4; ++k16) {
            uint32_t ah[5][4], al[5][4], bh[2][2], bl[2][2];
            const uint32_t kbyte = (uint32_t)(k16 * 16 + 8 * (lane >> 4)) * 2;
#pragma unroll
            for (int mf = 0; mf < 5; ++mf) {
                uint32_t roff = (uint32_t)(mf * 16 + (lane & 15)) * 128;
                ldmx4(ah[mf], stg + swz(roff + kbyte));
                ldmx4(al[mf], stg + 10240 + swz(roff + kbyte));
            }
            {
                int n = n0 + (lane & 7) + 8 * (lane >> 4);
                uint32_t koff = (uint32_t)(k16 * 16 + 8 * ((lane >> 3) & 1)) * 2;
                uint32_t boff = swz((uint32_t)n * 128 + koff);
                uint32_t r4[4];
                ldmx4(r4, stg + 20480 + boff);
                bh[0][0] = r4[0]; bh[0][1] = r4[1]; bh[1][0] = r4[2]; bh[1][1] = r4[3];
                ldmx4(r4, stg + 28672 + boff);
                bl[0][0] = r4[0]; bl[0][1] = r4[1]; bl[1][0] = r4[2]; bl[1][1] = r4[3];
            }
#pragma unroll
            for (int mf = 0; mf < 5; ++mf)
#pragma unroll
                for (int nf = 0; nf < 2; ++nf) {
                    mma16816(acc[mf][nf], ah[mf], bh[nf]);
                    mma16816(acc[mf][nf], ah[mf], bl[nf]);
                    mma16816(acc[mf][nf], al[mf], bh[nf]);
                }
        }
        cp_wait0();
        __syncthreads();
    }

    float* ep = (float*)smem;
#pragma unroll
    for (int mf = 0; mf < 5; ++mf)
#pragma unroll
        for (int nf = 0; nf < 2; ++nf) {
            int mm = mf * 16 + (lane >> 2);
            int nn = n0 + nf * 8 + (lane & 3) * 2;
            ep[nn * EP_STRIDE + mm]           = acc[mf][nf][0];
            ep[(nn + 1) * EP_STRIDE + mm]     = acc[mf][nf][1];
            ep[nn * EP_STRIDE + mm + 8]       = acc[mf][nf][2];
            ep[(nn + 1) * EP_STRIDE + mm + 8] = acc[mf][nf][3];
        }
    __syncthreads();

    if (tid < 64) {
        const int p = p0 + tid;
        float a[NCLS];
#pragma unroll
        for (int i = 0; i < NCLS; ++i) a[i] = ep[tid * EP_STRIDE + i] + __ldg(&b2[i]);
        float m = a[0];
#pragma unroll
        for (int i = 1; i < NCLS; ++i) m = fmaxf(m, a[i]);
        float ssum = 0.f;
#pragma unroll
        for (int i = 0; i < NCLS; ++i) { float e = expf(a[i] - m); a[i] = e; ssum += e; }
        const float inv = 1.f / ssum;
        int b = p >> 12;
        int rem = p & 4095;
        int y = rem >> 6;
        int w = rem & 63;
#pragma unroll
        for (int r1 = 0; r1 < 8; ++r1) {
            size_t base = ((size_t)(b * HI) + y * 8 + r1) * WI + w * 8;
#pragma unroll
            for (int r2 = 0; r2 < 8; ++r2) {
                float pr = a[r1 * 8 + r2] * inv;
                g_scores[base + r2] = (pr >= CONF) ? pr : 0.f;
            }
        }
    }
}

// ---------------- fused row+col max (radius 4) -> init mask ----------------
__global__ __launch_bounds__(256) void k_initmask() {
    const int x0 = blockIdx.x * 64;
    const int y0 = blockIdx.y * 32;
    const int b  = blockIdx.z;
    const int tid = threadIdx.x;
    __shared__ float sm[40][72];
    __shared__ float rm[40][64];
    for (int idx = tid; idx < 40 * 72; idx += 256) {
        int ly = idx / 72, j = idx - ly * 72;
        int gy = y0 - 4 + ly, gx = x0 - 4 + j;
        sm[ly][j] = (gy >= 0 && gy < HI && gx >= 0 && gx < WI)
            ? g_scores[((size_t)b * HI + gy) * WI + gx] : -FLT_MAX;
    }
    __syncthreads();
    for (int idx = tid; idx < 40 * 64; idx += 256) {
        int ly = idx >> 6, lx = idx & 63;
        float m = sm[ly][lx];
#pragma unroll
        for (int d = 1; d <= 8; ++d) m = fmaxf(m, sm[ly][lx + d]);
        rm[ly][lx] = m;
    }
    __syncthreads();
    for (int idx = tid; idx < 32 * 64; idx += 256) {
        int oy = idx >> 6, ox = idx & 63;
        float m = rm[oy][ox];
#pragma unroll
        for (int d = 1; d <= 8; ++d) m = fmaxf(m, rm[oy + d][ox]);
        size_t g = ((size_t)b * HI + y0 + oy) * WI + x0 + ox;
        float s = g_scores[g];
        g_mask_a[g] = (s == m && s > 0.f) ? 1 : 0;
    }
}

// ---------------- one NMS iteration, bit-packed masks (last=1 emits output) -------
// H coords: halo-8 rows y 0..47, bit x 0..47. S coords: halo-4, sy=yH-4, sx=xH-4.
__global__ __launch_bounds__(256) void k_nms_iter(int flip, int last, float* __restrict__ out) {
    const unsigned char* min_ = flip ? g_mask_b : g_mask_a;
    unsigned char*       mout = flip ? g_mask_a : g_mask_b;
    const int x0 = blockIdx.x * 32;
    const int y0 = blockIdx.y * 32;
    const int b  = blockIdx.z;
    const int tid = threadIdx.x;

    __shared__ unsigned char msk_b[48][48];
    __shared__ unsigned long long dil_s[48];
    __shared__ unsigned long long sup_s[40];   // indexed by sy (H row sy+4)
    __shared__ float ssc[40][41];
    __shared__ float rmx[40][33];

    // load mask bytes (halo 8)
    for (int idx = tid; idx < 48 * 48; idx += 256) {
        int y = idx / 48, x = idx - (idx / 48) * 48;
        int gy = y0 - 8 + y, gx = x0 - 8 + x;
        msk_b[y][x] = (gy >= 0 && gy < HI && gx >= 0 && gx < WI)
            ? min_[((size_t)b * HI + gy) * WI + gx] : 0;
    }
    // load scores (halo 4): 40x40
    for (int idx = tid; idx < 1600; idx += 256) {
        int sy = idx / 40, sx = idx - (idx / 40) * 40;
        int gy = y0 - 4 + sy, gx = x0 - 4 + sx;
        ssc[sy][sx] = (gy >= 0 && gy < HI && gx >= 0 && gx < WI)
            ? g_scores[((size_t)b * HI + gy) * WI + gx] : 0.f;
    }
    __syncthreads();
    // pack rows to bits + row dilation (radius 4)
    if (tid < 48) {
        const uint32_t* rw = (const uint32_t*)&msk_b[tid][0];
        unsigned long long m = 0;
#pragma unroll
        for (int i = 0; i < 12; ++i) {
            uint32_t nib = ((rw[i] & 0x01010101u) * 0x01020408u) >> 24;   // b0|b1<<1|b2<<2|b3<<3
            m |= (unsigned long long)(nib & 0xFu) << (4 * i);
        }
        unsigned long long d = m;
#pragma unroll
        for (int s = 1; s <= 4; ++s) d |= (m << s) | (m >> s);
        dil_s[tid] = d;
    }
    __syncthreads();
    // column dilation (radius 4): sup for H rows 4..43
    if (tid < 40) {
        unsigned long long s = dil_s[tid];
#pragma unroll
        for (int dd = 1; dd <= 8; ++dd) s |= dil_s[tid + dd];
        sup_s[tid] = s;
    }
    __syncthreads();
    // row max of suppressed scores: sy 0..39, rx 0..31; window sx = rx..rx+8,
    // sup bit index = sx + 4.
    for (int idx = tid; idx < 1280; idx += 256) {
        int sy = idx >> 5, rx = idx & 31;
        unsigned long long bits = sup_s[sy] >> (rx + 4);
        float m = 0.f;
#pragma unroll
        for (int d = 0; d < 9; ++d) {
            float val = ((bits >> d) & 1ull) ? 0.f : ssc[sy][rx + d];
            m = fmaxf(m, val);
        }
        rmx[sy][rx] = m;
    }
    __syncthreads();
    // col max + update: core cy,cx 0..31; rmx rows cy..cy+8 at col cx.
    for (int idx = tid; idx < 1024; idx += 256) {
        int cy = idx >> 5, cx = idx & 31;
        float m = 0.f;
#pragma unroll
        for (int d = 0; d < 9; ++d) m = fmaxf(m, rmx[cy + d][cx]);
        unsigned int supb = (unsigned int)((sup_s[cy + 4] >> (cx + 8)) & 1ull);
        float v = supb ? 0.f : ssc[cy + 4][cx + 4];
        unsigned char nm = (v == m && v > 0.f) ? 1 : 0;
        unsigned char o = msk_b[cy + 8][cx + 8] | (unsigned char)(nm & (supb ? 0u : 1u));
        int gy = y0 + cy, gx = x0 + cx;
        if (!last) {
            mout[((size_t)b * HI + gy) * WI + gx] = o;
        } else {
            bool border = (gy >= 4 && gy < HI - 4 && gx >= 4 && gx < WI - 4);
            out[((size_t)b * HI + gy) * WI + gx] = (o && border) ? ssc[cy + 4][cx + 4] : 0.f;
        }
    }
}

// ---------------- launch ----------------
extern "C" void kernel_launch(void* const* d_in, const int* in_sizes, int n_in,
                              void* d_out, int out_size) {
    const float* x  = (const float*)d_in[0];
    const float* w1 = (const float*)d_in[1];
    const float* b1 = (const float*)d_in[2];
    const float* w2 = (const float*)d_in[3];
    const float* b2 = (const float*)d_in[4];
    float* out = (float*)d_out;

    cudaFuncSetAttribute(k_conv1_mma, cudaFuncAttributeMaxDynamicSharedMemorySize, SMEM_C1);
    cudaFuncSetAttribute(k_conv2_mma, cudaFuncAttributeMaxDynamicSharedMemorySize, SMEM_C2);

    k_prep_w<<<1232, 256>>>(w1, w2);
    k_prep_x<<<dim3(66, 32), 256>>>(x);
    k_conv1_mma<<<dim3(2, 32, 32), 256, SMEM_C1>>>(b1);
    k_conv2_mma<<<2048, 128, SMEM_C2>>>(b2);
    k_initmask<<<dim3(8, 16, 32), 256>>>();
    for (int i = 0; i < 8; ++i)
        k_nms_iter<<<dim3(16, 16, 32), 256>>>(i & 1, (i == 7) ? 1 : 0, out);
}

// round 17
// speedup vs baseline: 1.3974x; 1.1242x over previous
#include <cuda_runtime.h>
#include <cuda_bf16.h>
#include <cstdint>
#include <cstddef>
#include <cfloat>

// Problem constants
#define BB   32
#define CIN  128
#define MID  256
#define HH   64
#define WW   64
#define NCLS 65
#define HI   512
#define WI   512
#define CONF 0.015f

// ---------------- scratch (device globals) ----------------
__device__ __nv_bfloat16 g_hhi[(size_t)BB * HH * WW * MID];  // [px][oc] hi
__device__ __nv_bfloat16 g_hlo[(size_t)BB * HH * WW * MID];  // [px][oc] lo
__device__ __nv_bfloat16 g_whi[MID * 1152];                  // [oc][(r*3+s)*128+c]
__device__ __nv_bfloat16 g_wlo[MID * 1152];
__device__ __nv_bfloat16 g_w2hi[80 * 256];                   // [cls(pad80)][oc]
__device__ __nv_bfloat16 g_w2lo[80 * 256];
// channel-last activations, y and x padded by 1 each side: [b][yy=0..65][ww=0..65][c]
__device__ __nv_bfloat16 g_xc_hi[(size_t)BB * 66 * 66 * 128];
__device__ __nv_bfloat16 g_xc_lo[(size_t)BB * 66 * 66 * 128];
__device__ float g_scores[(size_t)BB * HI * WI];
// bit-packed masks: 16 x u32 per image row
__device__ uint32_t g_mp_a[(size_t)BB * HI * 16];
__device__ uint32_t g_mp_b[(size_t)BB * HI * 16];

// ---------------- small PTX helpers (all sm_80+ standard) ----------------
__device__ __forceinline__ uint32_t smem_to_u32(const void* p) {
    uint32_t a;
    asm("{ .reg .u64 t; cvta.to.shared.u64 t, %1; cvt.u32.u64 %0, t; }" : "=r"(a) : "l"(p));
    return a;
}
__device__ __forceinline__ void cp_async16(uint32_t dst, const void* src) {
    asm volatile("cp.async.cg.shared.global [%0], [%1], 16;" :: "r"(dst), "l"(src));
}
__device__ __forceinline__ void cp_commit() { asm volatile("cp.async.commit_group;"); }
__device__ __forceinline__ void cp_wait0()  { asm volatile("cp.async.wait_group 0;"); }
__device__ __forceinline__ void cp_wait1()  { asm volatile("cp.async.wait_group 1;"); }

__device__ __forceinline__ void ldmx4(uint32_t* r, uint32_t addr) {
    asm volatile("ldmatrix.sync.aligned.m8n8.x4.shared.b16 {%0,%1,%2,%3}, [%4];"
                 : "=r"(r[0]), "=r"(r[1]), "=r"(r[2]), "=r"(r[3]) : "r"(addr));
}
__device__ __forceinline__ void mma16816(float* c, const uint32_t* a, const uint32_t* b) {
    asm volatile("mma.sync.aligned.m16n8k16.row.col.f32.bf16.bf16.f32 "
                 "{%0,%1,%2,%3}, {%4,%5,%6,%7}, {%8,%9}, {%0,%1,%2,%3};"
                 : "+f"(c[0]), "+f"(c[1]), "+f"(c[2]), "+f"(c[3])
                 : "r"(a[0]), "r"(a[1]), "r"(a[2]), "r"(a[3]), "r"(b[0]), "r"(b[1]));
}
__device__ __forceinline__ uint32_t swz(uint32_t off) { return off ^ ((off >> 3) & 0x70); }
__device__ __forceinline__ unsigned short bfu(float v) {
    __nv_bfloat16 h = __float2bfloat16_rn(v);
    return *(unsigned short*)&h;
}
__device__ __forceinline__ float bff(unsigned short u) {
    __nv_bfloat16 h = *(__nv_bfloat16*)&u;
    return __bfloat162float(h);
}

// ---------------- prep kernels ----------------
// blocks [0,1152): w1 split; blocks [1152,1232): w2 split.
__global__ void k_prep_w(const float* __restrict__ w1, const float* __restrict__ w2) {
    if (blockIdx.x < 1152) {
        int idx = blockIdx.x * 256 + threadIdx.x;      // 256*1152
        int oc = idx / 1152;
        int rem = idx - oc * 1152;
        int rs = rem >> 7, c = rem & 127;
        float v = w1[oc * 1152 + c * 9 + rs];
        __nv_bfloat16 hi = __float2bfloat16_rn(v);
        g_whi[idx] = hi;
        g_wlo[idx] = __float2bfloat16_rn(v - __bfloat162float(hi));
    } else {
        int idx = (blockIdx.x - 1152) * 256 + threadIdx.x;  // 80*256
        int cls = idx >> 8;
        float v = (cls < NCLS) ? w2[idx] : 0.f;
        __nv_bfloat16 hi = __float2bfloat16_rn(v);
        g_w2hi[idx] = hi;
        g_w2lo[idx] = __float2bfloat16_rn(v - __bfloat162float(hi));
    }
}

// Transpose x to channel-last, padded by 1 in y and x: g_xc[b][yy][ww][c].
__global__ __launch_bounds__(256) void k_prep_x(const float* __restrict__ x) {
    __shared__ float sm[128][65];
    const int yy = blockIdx.x;   // 0..65
    const int b  = blockIdx.y;
    const int tid = threadIdx.x;
    const int y = yy - 1;
    const bool valid_y = (y >= 0 && y < HH);
    if (valid_y) {
        for (int idx = tid; idx < 2048; idx += 256) {
            int c = idx >> 4, v = idx & 15;
            float4 val = *(const float4*)&x[(((size_t)b * CIN + c) * HH + y) * WW + v * 4];
            sm[c][v * 4 + 0] = val.x; sm[c][v * 4 + 1] = val.y;
            sm[c][v * 4 + 2] = val.z; sm[c][v * 4 + 3] = val.w;
        }
    }
    __syncthreads();
    for (int idx = tid; idx < 66 * 16; idx += 256) {   // 66 ww x 16 cvec
        int ww = idx >> 4, cv = idx & 15;
        int c0 = cv * 8;
        int xw = ww - 1;
        union { unsigned short u16[8]; uint4 v; } Hq, Lq;
        if (valid_y && xw >= 0 && xw < WW) {
#pragma unroll
            for (int e = 0; e < 8; ++e) {
                float vv = sm[c0 + e][xw];
                unsigned short h = bfu(vv);
                Hq.u16[e] = h;
                Lq.u16[e] = bfu(vv - bff(h));
            }
        } else {
            Hq.v = make_uint4(0, 0, 0, 0);
            Lq.v = make_uint4(0, 0, 0, 0);
        }
        size_t ofs = (((size_t)b * 66 + yy) * 66 + ww) * 128 + c0;
        *(uint4*)&g_xc_hi[ofs] = Hq.v;
        *(uint4*)&g_xc_lo[ofs] = Lq.v;
    }
}

// ---------------- conv1 via mma.sync (3-stage pipeline) ----------
#define STG_BYTES 65536
#define SMEM_C1 (3 * STG_BYTES)
__global__ __launch_bounds__(256, 1) void k_conv1_mma(const float* __restrict__ b1) {
    extern __shared__ char smem[];
    const uint32_t smem_u = smem_to_u32(smem);
    const int tid = threadIdx.x;
    const int lane = tid & 31;
    const int wid = tid >> 5;
    const int warpM = wid & 1;
    const int warpN = wid >> 1;
    const int o0g = blockIdx.x * 128;
    const int py0 = blockIdx.y * 2;
    const int bb  = blockIdx.z;

    float acc[4][4][4];
#pragma unroll
    for (int i = 0; i < 4; ++i)
#pragma unroll
        for (int j = 0; j < 4; ++j)
#pragma unroll
            for (int e = 0; e < 4; ++e) acc[i][j][e] = 0.f;

    auto fill = [&](int t, int buf) {
        const int rs = t >> 1;
        const int c0 = (t & 1) * 64;
        const int r = rs / 3, s = rs - r * 3;
        const uint32_t stg = smem_u + buf * STG_BYTES;
#pragma unroll
        for (int i = 0; i < 8; ++i) {
            int idx = tid + i * 256;
            int half = idx >> 10;
            int row  = (idx >> 3) & 127;
            int v    = idx & 7;
            const __nv_bfloat16* wseg = half ? g_wlo : g_whi;
            const void* src = wseg + (size_t)(o0g + row) * 1152 + rs * 128 + c0 + v * 8;
            cp_async16(stg + half * 16384 + swz((uint32_t)(row * 128 + v * 16)), src);
        }
        const size_t xb = (size_t)bb * 66;
#pragma unroll
        for (int i = 0; i < 8; ++i) {
            int idx = tid + i * 256;
            int half = idx >> 10;
            int row  = (idx >> 3) & 127;
            int v    = idx & 7;
            int j = row >> 6, w = row & 63;
            const __nv_bfloat16* xseg = half ? g_xc_lo : g_xc_hi;
            const void* src = xseg + ((xb + (py0 + j + r)) * 66 + (w + s)) * 128 + c0 + v * 8;
            cp_async16(stg + 32768 + half * 16384 + swz((uint32_t)(row * 128 + v * 16)), src);
        }
        cp_commit();
    };

    fill(0, 0);
    fill(1, 1);

    const int m0w = warpM * 64;
    const int n0w = warpN * 32;

    for (int t = 0; t < 18; ++t) {
        if (t + 1 < 18) cp_wait1(); else cp_wait0();
        __syncthreads();
        const uint32_t stg = smem_u + (t % 3) * STG_BYTES;
#pragma unroll
        for (int k16 = 0; k16 < 4; ++k16) {
            uint32_t afh[4][4], afl[4][4], bfh[4][2], bfl[4][2];
            const uint32_t kbyte = (uint32_t)(k16 * 16 + 8 * (lane >> 4)) * 2;
#pragma unroll
            for (int mf = 0; mf < 4; ++mf) {
                uint32_t roff = (uint32_t)(m0w + mf * 16 + (lane & 15)) * 128;
                ldmx4(afh[mf], stg + swz(roff + kbyte));
                ldmx4(afl[mf], stg + 16384 + swz(roff + kbyte));
            }
#pragma unroll
            for (int pair = 0; pair < 2; ++pair) {
                int n = n0w + pair * 16 + (lane & 7) + 8 * (lane >> 4);
                uint32_t koff = (uint32_t)(k16 * 16 + 8 * ((lane >> 3) & 1)) * 2;
                uint32_t boff = swz((uint32_t)n * 128 + koff);
                uint32_t r4[4];
                ldmx4(r4, stg + 32768 + boff);
                bfh[pair * 2][0] = r4[0]; bfh[pair * 2][1] = r4[1];
                bfh[pair * 2 + 1][0] = r4[2]; bfh[pair * 2 + 1][1] = r4[3];
                ldmx4(r4, stg + 49152 + boff);
                bfl[pair * 2][0] = r4[0]; bfl[pair * 2][1] = r4[1];
                bfl[pair * 2 + 1][0] = r4[2]; bfl[pair * 2 + 1][1] = r4[3];
            }
#pragma unroll
            for (int mf = 0; mf < 4; ++mf)
#pragma unroll
                for (int nf = 0; nf < 4; ++nf) {
                    mma16816(acc[mf][nf], afh[mf], bfh[nf]);
                    mma16816(acc[mf][nf], afh[mf], bfl[nf]);
                    mma16816(acc[mf][nf], afl[mf], bfh[nf]);
                }
        }
        if (t + 2 < 18) fill(t + 2, (t + 2) % 3);
    }

    // ---- epilogue: stage [64 px][128 oc], bias+relu, emit bf16 hi/lo ----
    float* ep = (float*)smem;
    const size_t pxbase = (size_t)bb * 4096 + (size_t)py0 * 64;
#pragma unroll
    for (int half = 0; half < 2; ++half) {
        __syncthreads();
        if ((warpN >> 1) == half) {
            const int nloc = (warpN & 1) * 32;
#pragma unroll
            for (int mf = 0; mf < 4; ++mf)
#pragma unroll
                for (int nf = 0; nf < 4; ++nf) {
                    int mm = m0w + mf * 16 + (lane >> 2);
                    int nn = nloc + nf * 8 + (lane & 3) * 2;
                    ep[nn * 132 + mm]           = acc[mf][nf][0];
                    ep[(nn + 1) * 132 + mm]     = acc[mf][nf][1];
                    ep[nn * 132 + mm + 8]       = acc[mf][nf][2];
                    ep[(nn + 1) * 132 + mm + 8] = acc[mf][nf][3];
                }
        }
        __syncthreads();
#pragma unroll
        for (int i = 0; i < 8; ++i) {
            int idx = tid + i * 256;
            int row = idx >> 5, vo = idx & 31;
            float4 bv = *(const float4*)&b1[o0g + vo * 4];
            float v0 = fmaxf(ep[row * 132 + vo * 4 + 0] + bv.x, 0.f);
            float v1 = fmaxf(ep[row * 132 + vo * 4 + 1] + bv.y, 0.f);
            float v2 = fmaxf(ep[row * 132 + vo * 4 + 2] + bv.z, 0.f);
            float v3 = fmaxf(ep[row * 132 + vo * 4 + 3] + bv.w, 0.f);
            union { unsigned short u[4]; uint2 v; } Hq, Lq;
            Hq.u[0] = bfu(v0); Lq.u[0] = bfu(v0 - bff(Hq.u[0]));
            Hq.u[1] = bfu(v1); Lq.u[1] = bfu(v1 - bff(Hq.u[1]));
            Hq.u[2] = bfu(v2); Lq.u[2] = bfu(v2 - bff(Hq.u[2]));
            Hq.u[3] = bfu(v3); Lq.u[3] = bfu(v3 - bff(Hq.u[3]));
            size_t px = pxbase + half * 64 + row;
            *(uint2*)&g_hhi[px * MID + o0g + vo * 4] = Hq.v;
            *(uint2*)&g_hlo[px * MID + o0g + vo * 4] = Lq.v;
        }
    }
}

// ---------------- conv2: 128 threads / 64 px per CTA, A+B double-buffered ------
#define ST2_BYTES 36864
#define SMEM_C2   (2 * ST2_BYTES)
#define EP_STRIDE 85
__global__ __launch_bounds__(128, 1) void k_conv2_mma(const float* __restrict__ b2) {
    extern __shared__ char smem[];
    const uint32_t smem_u = smem_to_u32(smem);
    const int tid = threadIdx.x;
    const int lane = tid & 31;
    const int wid = tid >> 5;          // 0..3
    const int n0 = wid * 16;
    const int p0 = blockIdx.x * 64;

    auto fill = [&](int kc, int buf) {
        const uint32_t stg = smem_u + buf * ST2_BYTES;
        for (int idx = tid; idx < 1280; idx += 128) {
            int half = idx / 640;
            int rr = idx - half * 640;
            int row = rr >> 3, v = rr & 7;
            const __nv_bfloat16* src = (half ? g_w2lo : g_w2hi) + row * 256 + kc * 64 + v * 8;
            cp_async16(stg + half * 10240 + swz((uint32_t)(row * 128 + v * 16)), src);
        }
        for (int idx = tid; idx < 1024; idx += 128) {
            int half = idx >> 9;
            int row  = (idx >> 3) & 63;
            int v    = idx & 7;
            const __nv_bfloat16* src = (half ? g_hlo : g_hhi) + (size_t)(p0 + row) * 256 + kc * 64 + v * 8;
            cp_async16(stg + 20480 + half * 8192 + swz((uint32_t)(row * 128 + v * 16)), src);
        }
        cp_commit();
    };
    fill(0, 0);
    cp_wait0();
    __syncthreads();

    float acc[5][2][4];
#pragma unroll
    for (int i = 0; i < 5; ++i)
#pragma unroll
        for (int j = 0; j < 2; ++j)
#pragma unroll
            for (int e = 0; e < 4; ++e) acc[i][j][e] = 0.f;

    for (int kc = 0; kc < 4; ++kc) {
        const int cur = kc & 1;
        if (kc + 1 < 4) fill(kc + 1, cur ^ 1);
        const uint32_t stg = smem_u + cur * ST2_BYTES;
#pragma unroll
        for (int k16 = 0; k16 < 4; ++k16) {
            uint32_t ah[5][4], al[5][4], bh[2][2], bl[2][2];
            const uint32_t kbyte = (uint32_t)(k16 * 16 + 8 * (lane >> 4)) * 2;
#pragma unroll
            for (int mf = 0; mf < 5; ++mf) {
                uint32_t roff = (uint32_t)(mf * 16 + (lane & 15)) * 128;
                ldmx4(ah[mf], stg + swz(roff + kbyte));
                ldmx4(al[mf], stg + 10240 + swz(roff + kbyte));
            }
            {
                int n = n0 + (lane & 7) + 8 * (lane >> 4);
                uint32_t koff = (uint32_t)(k16 * 16 + 8 * ((lane >> 3) & 1)) * 2;
                uint32_t boff = swz((uint32_t)n * 128 + koff);
                uint32_t r4[4];
                ldmx4(r4, stg + 20480 + boff);
                bh[0][0] = r4[0]; bh[0][1] = r4[1]; bh[1][0] = r4[2]; bh[1][1] = r4[3];
                ldmx4(r4, stg + 28672 + boff);
                bl[0][0] = r4[0]; bl[0][1] = r4[1]; bl[1][0] = r4[2]; bl[1][1] = r4[3];
            }
#pragma unroll
            for (int mf = 0; mf < 5; ++mf)
#pragma unroll
                for (int nf = 0; nf < 2; ++nf) {
                    mma16816(acc[mf][nf], ah[mf], bh[nf]);
                    mma16816(acc[mf][nf], ah[mf], bl[nf]);
                    mma16816(acc[mf][nf], al[mf], bh[nf]);
                }
        }
        cp_wait0();
        __syncthreads();
    }

    float* ep = (float*)smem;
#pragma unroll
    for (int mf = 0; mf < 5; ++mf)
#pragma unroll
        for (int nf = 0; nf < 2; ++nf) {
            int mm = mf * 16 + (lane >> 2);
            int nn = n0 + nf * 8 + (lane & 3) * 2;
            ep[nn * EP_STRIDE + mm]           = acc[mf][nf][0];
            ep[(nn + 1) * EP_STRIDE + mm]     = acc[mf][nf][1];
            ep[nn * EP_STRIDE + mm + 8]       = acc[mf][nf][2];
            ep[(nn + 1) * EP_STRIDE + mm + 8] = acc[mf][nf][3];
        }
    __syncthreads();

    if (tid < 64) {
        const int p = p0 + tid;
        float a[NCLS];
#pragma unroll
        for (int i = 0; i < NCLS; ++i) a[i] = ep[tid * EP_STRIDE + i] + __ldg(&b2[i]);
        float m = a[0];
#pragma unroll
        for (int i = 1; i < NCLS; ++i) m = fmaxf(m, a[i]);
        float ssum = 0.f;
#pragma unroll
        for (int i = 0; i < NCLS; ++i) { float e = expf(a[i] - m); a[i] = e; ssum += e; }
        const float inv = 1.f / ssum;
        int b = p >> 12;
        int rem = p & 4095;
        int y = rem >> 6;
        int w = rem & 63;
#pragma unroll
        for (int r1 = 0; r1 < 8; ++r1) {
            size_t base = ((size_t)(b * HI) + y * 8 + r1) * WI + w * 8;
#pragma unroll
            for (int r2 = 0; r2 < 8; ++r2) {
                float pr = a[r1 * 8 + r2] * inv;
                g_scores[base + r2] = (pr >= CONF) ? pr : 0.f;
            }
        }
    }
}

// ---------------- fused row+col max (radius 4) -> init mask (packed words) -------
__global__ __launch_bounds__(256) void k_initmask() {
    const int x0 = blockIdx.x * 64;
    const int y0 = blockIdx.y * 32;
    const int b  = blockIdx.z;
    const int tid = threadIdx.x;
    __shared__ float sm[40][72];
    __shared__ float rm[40][64];
    for (int idx = tid; idx < 40 * 72; idx += 256) {
        int ly = idx / 72, j = idx - ly * 72;
        int gy = y0 - 4 + ly, gx = x0 - 4 + j;
        sm[ly][j] = (gy >= 0 && gy < HI && gx >= 0 && gx < WI)
            ? g_scores[((size_t)b * HI + gy) * WI + gx] : -FLT_MAX;
    }
    __syncthreads();
    for (int idx = tid; idx < 40 * 64; idx += 256) {
        int ly = idx >> 6, lx = idx & 63;
        float m = sm[ly][lx];
#pragma unroll
        for (int d = 1; d <= 8; ++d) m = fmaxf(m, sm[ly][lx + d]);
        rm[ly][lx] = m;
    }
    __syncthreads();
    // warp covers ox = 32*(w&1) + lane, oy = 4i + (w>>1); ballot packs a word.
    for (int idx = tid; idx < 32 * 64; idx += 256) {
        int oy = idx >> 6, ox = idx & 63;
        float m = rm[oy][ox];
#pragma unroll
        for (int d = 1; d <= 8; ++d) m = fmaxf(m, rm[oy + d][ox]);
        float s = sm[oy + 4][ox + 4];
        unsigned bit = (s == m && s > 0.f) ? 1u : 0u;
        unsigned word = __ballot_sync(0xFFFFFFFFu, bit);
        if ((tid & 31) == 0)
            g_mp_a[((size_t)b * HI + y0 + oy) * 16 + (x0 >> 5) + ((tid >> 5) & 1)] = word;
    }
}

// ---------------- one NMS iteration, fully bit-packed (last=1 emits output) -------
__global__ __launch_bounds__(256) void k_nms_iter(int flip, int last, float* __restrict__ out) {
    const uint32_t* min_ = flip ? g_mp_b : g_mp_a;
    uint32_t*       mout = flip ? g_mp_a : g_mp_b;
    const int x0 = blockIdx.x * 32;
    const int y0 = blockIdx.y * 32;
    const int b  = blockIdx.z;
    const int tid = threadIdx.x;
    const int wbase = x0 >> 5;

    __shared__ unsigned long long mrow[48];
    __shared__ unsigned long long dil_s[48];
    __shared__ unsigned long long sup_s[40];
    __shared__ float ssc[40][41];
    __shared__ float rmx[40][33];

    // load packed mask halo rows: 48-bit window starting at gx = x0-8
    if (tid < 48) {
        int gy = y0 - 8 + tid;
        unsigned long long m = 0;
        if (gy >= 0 && gy < HI) {
            const uint32_t* row = min_ + ((size_t)b * HI + gy) * 16;
            uint32_t wm1 = (wbase >= 1) ? row[wbase - 1] : 0u;
            uint32_t w0  = row[wbase];
            uint32_t wp1 = (wbase + 1 < 16) ? row[wbase + 1] : 0u;
            m = ((unsigned long long)wm1 >> 24)
              | ((unsigned long long)w0 << 8)
              | ((unsigned long long)wp1 << 40);
            m &= 0xFFFFFFFFFFFFull;       // 48 valid bits
        }
        mrow[tid] = m;
        unsigned long long d = m;
#pragma unroll
        for (int s = 1; s <= 4; ++s) d |= (m << s) | (m >> s);
        dil_s[tid] = d;
    }
    // load scores (halo 4): 40x40
    for (int idx = tid; idx < 1600; idx += 256) {
        int sy = idx / 40, sx = idx - (idx / 40) * 40;
        int gy = y0 - 4 + sy, gx = x0 - 4 + sx;
        ssc[sy][sx] = (gy >= 0 && gy < HI && gx >= 0 && gx < WI)
            ? g_scores[((size_t)b * HI + gy) * WI + gx] : 0.f;
    }
    __syncthreads();
    // column dilation (radius 4): sup for H rows 4..43
    if (tid < 40) {
        unsigned long long s = dil_s[tid];
#pragma unroll
        for (int dd = 1; dd <= 8; ++dd) s |= dil_s[tid + dd];
        sup_s[tid] = s;
    }
    __syncthreads();
    // row max of suppressed scores: sy 0..39, rx 0..31
    for (int idx = tid; idx < 1280; idx += 256) {
        int sy = idx >> 5, rx = idx & 31;
        unsigned long long bits = sup_s[sy] >> (rx + 4);
        float m = 0.f;
#pragma unroll
        for (int d = 0; d < 9; ++d) {
            float val = ((bits >> d) & 1ull) ? 0.f : ssc[sy][rx + d];
            m = fmaxf(m, val);
        }
        rmx[sy][rx] = m;
    }
    __syncthreads();
    // col max + update: warp = one row (cy), lane = cx; ballot packs output word.
    for (int idx = tid; idx < 1024; idx += 256) {
        int cy = idx >> 5, cx = idx & 31;
        float m = 0.f;
#pragma unroll
        for (int d = 0; d < 9; ++d) m = fmaxf(m, rmx[cy + d][cx]);
        unsigned supb = (unsigned)((sup_s[cy + 4] >> (cx + 8)) & 1ull);
        float v = supb ? 0.f : ssc[cy + 4][cx + 4];
        unsigned nm = (v == m && v > 0.f) ? 1u : 0u;
        unsigned mb = (unsigned)((mrow[cy + 8] >> (cx + 8)) & 1ull);
        unsigned o = mb | (nm & (supb ? 0u : 1u));
        if (!last) {
            unsigned word = __ballot_sync(0xFFFFFFFFu, o);
            if ((tid & 31) == 0)
                mout[((size_t)b * HI + y0 + cy) * 16 + wbase] = word;
        } else {
            int gy = y0 + cy, gx = x0 + cx;
            bool border = (gy >= 4 && gy < HI - 4 && gx >= 4 && gx < WI - 4);
            out[((size_t)b * HI + gy) * WI + gx] = (o && border) ? ssc[cy + 4][cx + 4] : 0.f;
        }
    }
}

// ---------------- launch ----------------
extern "C" void kernel_launch(void* const* d_in, const int* in_sizes, int n_in,
                              void* d_out, int out_size) {
    const float* x  = (const float*)d_in[0];
    const float* w1 = (const float*)d_in[1];
    const float* b1 = (const float*)d_in[2];
    const float* w2 = (const float*)d_in[3];
    const float* b2 = (const float*)d_in[4];
    float* out = (float*)d_out;

    cudaFuncSetAttribute(k_conv1_mma, cudaFuncAttributeMaxDynamicSharedMemorySize, SMEM_C1);
    cudaFuncSetAttribute(k_conv2_mma, cudaFuncAttributeMaxDynamicSharedMemorySize, SMEM_C2);

    k_prep_w<<<1232, 256>>>(w1, w2);
    k_prep_x<<<dim3(66, 32), 256>>>(x);
    k_conv1_mma<<<dim3(2, 32, 32), 256, SMEM_C1>>>(b1);
    k_conv2_mma<<<2048, 128, SMEM_C2>>>(b2);
    k_initmask<<<dim3(8, 16, 32), 256>>>();
    for (int i = 0; i < 8; ++i)
        k_nms_iter<<<dim3(16, 16, 32), 256>>>(i & 1, (i == 7) ? 1 : 0, out);
}